// round 14
// baseline (speedup 1.0000x reference)
#include <cuda_runtime.h>
#include <cuda_bf16.h>
#include <math.h>
#include <stdint.h>

// Problem constants
#define BB 2
#define NN 10000
#define HH 128
#define EE 128000
#define MM (BB*EE)          // 256000 rows
#define GDIM 384            // 3*H

// ---------------- scratch (device globals; no runtime allocation) -------------
__device__ float g_giA[(size_t)MM*768];
__device__ float g_giB[(size_t)MM*768];
__device__ float g_gh[(size_t)MM*384];
__device__ float g_y0[(size_t)MM*256];
__device__ float g_y1[(size_t)MM*256];
__device__ float g_hh[(size_t)MM*256];
__device__ float g_hb1[(size_t)MM*128];
__device__ float g_logits[MM];
__device__ float g_av[MM];
__device__ unsigned g_mxh[NN*BB];
__device__ unsigned g_mxs[NN*BB];
__device__ float g_sh[NN*BB];
__device__ float g_ss[NN*BB];

// bf16 hi/lo activation buffers
__device__ __nv_bfloat16 g_x0h[(size_t)MM*128], g_x0l[(size_t)MM*128];
__device__ __nv_bfloat16 g_x1h[(size_t)MM*128], g_x1l[(size_t)MM*128];
__device__ __nv_bfloat16 g_y0h[(size_t)MM*256], g_y0l[(size_t)MM*256];
__device__ __nv_bfloat16 g_y1h[(size_t)MM*256], g_y1l[(size_t)MM*256];
__device__ __nv_bfloat16 g_hb1h[(size_t)MM*128], g_hb1l[(size_t)MM*128];

// packed pre-split weights: layout [cb][kc][r(128)][c(32)]
// regions: wih0f 0 | wih0b 49152 | whh0f 98304 | whh0b 147456 |
//          whh1b 196608 | wih1f 245760 (K=256) | wih1b 344064 (K=256)
#define WPK_TOTAL 442368
__device__ __nv_bfloat16 g_wpk_h[WPK_TOTAL];
__device__ __nv_bfloat16 g_wpk_l[WPK_TOTAL];

// ---------------- helpers -----------------------------------------------------
__device__ __forceinline__ unsigned enc_f(float x) {
    unsigned u = __float_as_uint(x);
    return (u & 0x80000000u) ? ~u : (u | 0x80000000u);
}
__device__ __forceinline__ float dec_f(unsigned v) {
    return (v & 0x80000000u) ? __uint_as_float(v ^ 0x80000000u) : __uint_as_float(~v);
}
#define ENC_NEG_INF 0x007FFFFFu

__device__ __forceinline__ float sigmoidf_(float x) { return 1.0f / (1.0f + expf(-x)); }

__device__ __forceinline__ uint32_t smem_u32(const void* p) {
    uint32_t a;
    asm("{ .reg .u64 t; cvta.to.shared.u64 t, %1; cvt.u32.u64 %0, t; }" : "=r"(a) : "l"(p));
    return a;
}

#define LDMX4(r0, r1, r2, r3, addr) \
    asm volatile("ldmatrix.sync.aligned.m8n8.x4.shared.b16 {%0,%1,%2,%3}, [%4];" \
                 : "=r"(r0), "=r"(r1), "=r"(r2), "=r"(r3) : "r"(addr))

#define MMA_BF16(c, a0, a1, a2, a3, b0, b1) \
    asm volatile("mma.sync.aligned.m16n8k16.row.col.f32.bf16.bf16.f32 " \
                 "{%0,%1,%2,%3}, {%4,%5,%6,%7}, {%8,%9}, {%0,%1,%2,%3};" \
                 : "+f"((c)[0]), "+f"((c)[1]), "+f"((c)[2]), "+f"((c)[3]) \
                 : "r"(a0), "r"(a1), "r"(a2), "r"(a3), "r"(b0), "r"(b1))

#define CPA16(dst, src) \
    asm volatile("cp.async.cg.shared.global [%0], [%1], 16;" :: "r"(dst), "l"(src))
#define CPA_COMMIT() asm volatile("cp.async.commit_group;" ::: "memory")
#define CPA_WAIT1() asm volatile("cp.async.wait_group 1;" ::: "memory")

__device__ __forceinline__ void split_bf16(float x, __nv_bfloat16& hi, __nv_bfloat16& lo) {
    hi = __float2bfloat16_rn(x);
    lo = __float2bfloat16_rn(x - __bfloat162float(hi));
}

// ---------------- weight pre-split/pack: ALL weights in one launch ---------------
__global__ void pack_all(const float* __restrict__ wih0f, const float* __restrict__ wih0b,
                         const float* __restrict__ whh0f, const float* __restrict__ whh0b,
                         const float* __restrict__ whh1b,
                         const float* __restrict__ wih1f, const float* __restrict__ wih1b,
                         __nv_bfloat16* __restrict__ outh,
                         __nv_bfloat16* __restrict__ outl) {
    int idx = blockIdx.x * blockDim.x + threadIdx.x;
    if (idx >= WPK_TOTAL) return;
    const float* W; int base, K;
    if      (idx < 49152)  { W = wih0f; base = 0;      K = 128; }
    else if (idx < 98304)  { W = wih0b; base = 49152;  K = 128; }
    else if (idx < 147456) { W = whh0f; base = 98304;  K = 128; }
    else if (idx < 196608) { W = whh0b; base = 147456; K = 128; }
    else if (idx < 245760) { W = whh1b; base = 196608; K = 128; }
    else if (idx < 344064) { W = wih1f; base = 245760; K = 256; }
    else                   { W = wih1b; base = 344064; K = 256; }
    int li = idx - base;
    int nkc = K >> 5;
    int c = li & 31;
    int r = (li >> 5) & 127;
    int kcb = li >> 12;
    int kc = kcb % nkc, cb = kcb / nkc;
    float v = W[(size_t)(cb * 128 + r) * K + kc * 32 + c];
    __nv_bfloat16 hi, lo; split_bf16(v, hi, lo);
    outh[idx] = hi; outl[idx] = lo;
}

// ---------------- gather (writes bf16 hi/lo) ------------------------------------
__global__ void gather_kernel(const float4* __restrict__ h,
                              const int* __restrict__ tgt,
                              const int* __restrict__ src,
                              __nv_bfloat16* __restrict__ x0h, __nv_bfloat16* __restrict__ x0l,
                              __nv_bfloat16* __restrict__ x1h, __nv_bfloat16* __restrict__ x1l) {
    long long idx = (long long)blockIdx.x * blockDim.x + threadIdx.x;
    int q = (int)(idx & 31);
    long long be = idx >> 5;
    int e = (int)(be % EE);
    int b = (int)(be / EE);
    int t = tgt[e], s = src[e];
    float4 vt = h[((long long)b * NN + t) * 32 + q];
    float4 vs = h[((long long)b * NN + s) * 32 + q];
    __nv_bfloat16 hh_[4], ll_[4];
    long long o = be * 128 + q * 4;
    split_bf16(vt.x, hh_[0], ll_[0]); split_bf16(vt.y, hh_[1], ll_[1]);
    split_bf16(vt.z, hh_[2], ll_[2]); split_bf16(vt.w, hh_[3], ll_[3]);
    *(ulonglong1*)(x0h + o) = *(ulonglong1*)hh_;
    *(ulonglong1*)(x0l + o) = *(ulonglong1*)ll_;
    split_bf16(vs.x, hh_[0], ll_[0]); split_bf16(vs.y, hh_[1], ll_[1]);
    split_bf16(vs.z, hh_[2], ll_[2]); split_bf16(vs.w, hh_[3], ll_[3]);
    *(ulonglong1*)(x1h + o) = *(ulonglong1*)hh_;
    *(ulonglong1*)(x1l + o) = *(ulonglong1*)ll_;
}

// ---------------- bf16x3 HMMA GEMM, 2-stage cp.async, 2 CTAs/SM ------------------
#define SBF 40
#define TILE_B (128 * SBF * 2)
#define STAGE_B (4 * TILE_B)     // 40960
#define PSMEM (2 * STAGE_B)      // 81920

__global__ void __launch_bounds__(256, 2) sgemm_mma(
        const __nv_bfloat16* __restrict__ Ah, const __nv_bfloat16* __restrict__ Al,
        int lda,
        const __nv_bfloat16* __restrict__ Wh, const __nv_bfloat16* __restrict__ Wl,
        int nkc,
        float* __restrict__ C, int ldc) {
    extern __shared__ __align__(16) char smem[];
    uint32_t sb = smem_u32(smem);

    int tid = threadIdx.x;
    int lane = tid & 31;
    int wid = tid >> 5;
    int warp_m = wid & 3;
    int warp_n = wid >> 2;
    int rowBlk = blockIdx.y * 128;
    int cb = blockIdx.x;

    float c[2][8][4];
    #pragma unroll
    for (int i = 0; i < 2; i++)
        #pragma unroll
        for (int j = 0; j < 8; j++)
            #pragma unroll
            for (int q = 0; q < 4; q++) c[i][j][q] = 0.0f;

    auto issue = [&](int kc, int s) {
        #pragma unroll
        for (int q = 0; q < 8; q++) {
            int id = tid + q * 256;
            int tile = id >> 9;
            int rem = id & 511;
            int r = rem >> 2, c16 = rem & 3;
            uint32_t dst = sb + s * STAGE_B + tile * TILE_B + r * (SBF * 2) + c16 * 16;
            const __nv_bfloat16* src;
            if (tile == 0)
                src = Ah + (size_t)(rowBlk + r) * lda + kc * 32 + c16 * 8;
            else if (tile == 1)
                src = Al + (size_t)(rowBlk + r) * lda + kc * 32 + c16 * 8;
            else if (tile == 2)
                src = Wh + ((size_t)(cb * nkc + kc) << 12) + r * 32 + c16 * 8;
            else
                src = Wl + ((size_t)(cb * nkc + kc) << 12) + r * 32 + c16 * 8;
            CPA16(dst, src);
        }
    };

    int a_r = lane & 15, a_c = (lane >> 4) << 3;
    int b_r = (lane & 7) + ((lane >> 4) << 3);
    int b_c = ((lane >> 3) & 1) << 3;

    issue(0, 0);
    CPA_COMMIT();

    for (int kc = 0; kc < nkc; kc++) {
        if (kc + 1 < nkc) issue(kc + 1, (kc + 1) & 1);
        CPA_COMMIT();
        CPA_WAIT1();
        __syncthreads();

        uint32_t st = sb + (kc & 1) * STAGE_B;
        uint32_t uAh = st, uAl = st + TILE_B, uWh = st + 2 * TILE_B, uWl = st + 3 * TILE_B;

        #pragma unroll
        for (int ks = 0; ks < 2; ks++) {
            uint32_t ah[2][4], al[2][4];
            #pragma unroll
            for (int mt = 0; mt < 2; mt++) {
                uint32_t eoff = (uint32_t)((warp_m * 32 + mt * 16 + a_r) * SBF
                                           + ks * 16 + a_c) * 2;
                LDMX4(ah[mt][0], ah[mt][1], ah[mt][2], ah[mt][3], uAh + eoff);
                LDMX4(al[mt][0], al[mt][1], al[mt][2], al[mt][3], uAl + eoff);
            }
            #pragma unroll
            for (int np = 0; np < 4; np++) {
                uint32_t bh[4], bl[4];
                uint32_t eoff = (uint32_t)((warp_n * 64 + np * 16 + b_r) * SBF
                                           + ks * 16 + b_c) * 2;
                LDMX4(bh[0], bh[1], bh[2], bh[3], uWh + eoff);
                LDMX4(bl[0], bl[1], bl[2], bl[3], uWl + eoff);
                #pragma unroll
                for (int mt = 0; mt < 2; mt++) {
                    float* c0 = c[mt][np * 2];
                    float* c1 = c[mt][np * 2 + 1];
                    MMA_BF16(c0, ah[mt][0], ah[mt][1], ah[mt][2], ah[mt][3], bh[0], bh[1]);
                    MMA_BF16(c0, ah[mt][0], ah[mt][1], ah[mt][2], ah[mt][3], bl[0], bl[1]);
                    MMA_BF16(c0, al[mt][0], al[mt][1], al[mt][2], al[mt][3], bh[0], bh[1]);
                    MMA_BF16(c1, ah[mt][0], ah[mt][1], ah[mt][2], ah[mt][3], bh[2], bh[3]);
                    MMA_BF16(c1, ah[mt][0], ah[mt][1], ah[mt][2], ah[mt][3], bl[2], bl[3]);
                    MMA_BF16(c1, al[mt][0], al[mt][1], al[mt][2], al[mt][3], bh[2], bh[3]);
                }
            }
        }
        __syncthreads();
    }

    int colBlk = cb * 128;
    #pragma unroll
    for (int mt = 0; mt < 2; mt++) {
        int r = rowBlk + warp_m * 32 + mt * 16 + (lane >> 2);
        #pragma unroll
        for (int nt = 0; nt < 8; nt++) {
            int col = colBlk + warp_n * 64 + nt * 8 + (lane & 3) * 2;
            *(float2*)(C + (size_t)r * ldc + col) =
                make_float2(c[mt][nt][0], c[mt][nt][1]);
            *(float2*)(C + (size_t)(r + 8) * ldc + col) =
                make_float2(c[mt][nt][2], c[mt][nt][3]);
        }
    }
}

// ---------------- GRU pointwise (nullable fp32 out; optional bf16 hi/lo) ---------
__global__ void gru_pointwise(const float* __restrict__ gi, int gi_stride,
                              const float* __restrict__ gh,
                              const float* __restrict__ hp, int hp_stride,
                              const float* __restrict__ b_ih,
                              const float* __restrict__ b_hh,
                              float* __restrict__ out, int out_stride,
                              __nv_bfloat16* __restrict__ outh,
                              __nv_bfloat16* __restrict__ outl, int bf_stride) {
    long long idx = (long long)blockIdx.x * blockDim.x + threadIdx.x;
    int j = (int)(idx & 127);
    long long m = idx >> 7;
    const float* gir = gi + m * (long long)gi_stride;
    float ir = gir[j]        + b_ih[j];
    float iz = gir[128 + j]  + b_ih[128 + j];
    float in_ = gir[256 + j] + b_ih[256 + j];
    float hr, hz, hn;
    if (gh) {
        const float* ghr = gh + m * GDIM;
        hr = ghr[j]       + b_hh[j];
        hz = ghr[128 + j] + b_hh[128 + j];
        hn = ghr[256 + j] + b_hh[256 + j];
    } else {
        hr = b_hh[j]; hz = b_hh[128 + j]; hn = b_hh[256 + j];
    }
    float r = sigmoidf_(ir + hr);
    float z = sigmoidf_(iz + hz);
    float n = tanhf(in_ + r * hn);
    float hv = hp ? hp[m * (long long)hp_stride + j] : 0.0f;
    float o = (1.0f - z) * n + z * hv;
    if (out) out[m * (long long)out_stride + j] = o;
    if (outh) {
        __nv_bfloat16 hi, lo; split_bf16(o, hi, lo);
        outh[m * (long long)bf_stride + j] = hi;
        outl[m * (long long)bf_stride + j] = lo;
    }
}

// dual: two independent zero-state cells (gh = hp = null for both) in one launch
__global__ void gru_pointwise_dual(
        long long half_blocks,
        const float* __restrict__ giA, int giA_stride,
        const float* __restrict__ bihA, const float* __restrict__ bhhA,
        float* __restrict__ outA, int outA_stride,
        __nv_bfloat16* __restrict__ outAh, __nv_bfloat16* __restrict__ outAl, int bfA_stride,
        const float* __restrict__ giB, int giB_stride,
        const float* __restrict__ bihB, const float* __restrict__ bhhB,
        float* __restrict__ outB, int outB_stride,
        __nv_bfloat16* __restrict__ outBh, __nv_bfloat16* __restrict__ outBl, int bfB_stride) {
    long long blk = blockIdx.x;
    int jobB = (blk >= half_blocks);
    long long idx = (blk - (jobB ? half_blocks : 0)) * blockDim.x + threadIdx.x;
    int j = (int)(idx & 127);
    long long m = idx >> 7;
    const float* gi  = jobB ? giB : giA;
    int gis          = jobB ? giB_stride : giA_stride;
    const float* bih = jobB ? bihB : bihA;
    const float* bhh = jobB ? bhhB : bhhA;
    float* out       = jobB ? outB : outA;
    int outs         = jobB ? outB_stride : outA_stride;
    __nv_bfloat16* oh = jobB ? outBh : outAh;
    __nv_bfloat16* ol = jobB ? outBl : outAl;
    int bfs          = jobB ? bfB_stride : bfA_stride;

    const float* gir = gi + m * (long long)gis;
    float r = sigmoidf_(gir[j]        + bih[j]        + bhh[j]);
    float z = sigmoidf_(gir[128 + j]  + bih[128 + j]  + bhh[128 + j]);
    float n = tanhf(gir[256 + j] + bih[256 + j] + r * bhh[256 + j]);
    float o = (1.0f - z) * n;
    if (out) out[m * (long long)outs + j] = o;
    if (oh) {
        __nv_bfloat16 hi, lo; split_bf16(o, hi, lo);
        oh[m * (long long)bfs + j] = hi;
        ol[m * (long long)bfs + j] = lo;
    }
}

// ---------------- logits ---------------------------------------------------------
__global__ void logits_kernel(const float* __restrict__ hh,
                              const float* __restrict__ w_con,
                              const float* __restrict__ b_con,
                              float* __restrict__ logits) {
    long long gth = (long long)blockIdx.x * blockDim.x + threadIdx.x;
    long long warp = gth >> 5;
    int lane = (int)(gth & 31);
    const float* row = hh + warp * 256;
    float s = 0.0f;
    #pragma unroll
    for (int k = 0; k < 8; k++) s = fmaf(row[lane + k * 32], w_con[lane + k * 32], s);
    #pragma unroll
    for (int o = 16; o > 0; o >>= 1) s += __shfl_xor_sync(0xFFFFFFFFu, s, o);
    if (lane == 0) {
        float x = s + b_con[0];
        logits[warp] = 0.5f * x * (1.0f + erff(x * 0.70710678118654752440f));
    }
}

// ---------------- JAX threefry2x32 gumbel, partitionable mode -------------------
__device__ __forceinline__ void threefry2x32_dev(unsigned k0, unsigned k1,
                                                 unsigned& x0, unsigned& x1) {
    unsigned ks2 = k0 ^ k1 ^ 0x1BD11BDAu;
    x0 += k0; x1 += k1;
#define TFR(r) { x0 += x1; x1 = (x1 << (r)) | (x1 >> (32 - (r))); x1 ^= x0; }
#define TFG(a, b, c, d, A0, A1, INC) TFR(a) TFR(b) TFR(c) TFR(d) x0 += (A0); x1 += (A1) + (INC);
    TFG(13, 15, 26, 6,  k1,  ks2, 1u)
    TFG(17, 29, 16, 24, ks2, k0,  2u)
    TFG(13, 15, 26, 6,  k0,  k1,  3u)
    TFG(17, 29, 16, 24, k1,  ks2, 4u)
    TFG(13, 15, 26, 6,  ks2, k0,  5u)
#undef TFR
#undef TFG
}

__device__ __forceinline__ float bits_to_gumbel(unsigned bits) {
    float u = __uint_as_float((bits >> 9) | 0x3f800000u) - 1.0f;
    float v = fmaxf(u, 1.175494350822287508e-38f);
    return -logf(-logf(v));
}

// ---------------- init / segment softmax / scatter -------------------------------
__global__ void init_kernel(float* __restrict__ out,
                            unsigned* __restrict__ mxh, unsigned* __restrict__ mxs,
                            float* __restrict__ sh, float* __restrict__ ss) {
    int i = blockIdx.x * blockDim.x + threadIdx.x;
    if (i < BB * NN * HH) out[i] = 0.0f;
    if (i < NN * BB) { mxh[i] = ENC_NEG_INF; mxs[i] = ENC_NEG_INF; sh[i] = 0.0f; ss[i] = 0.0f; }
}

__global__ void prep_kernel(const float* __restrict__ logits,
                            const int* __restrict__ src,
                            float* __restrict__ av,
                            unsigned* __restrict__ mxh, unsigned* __restrict__ mxs) {
    int f = blockIdx.x * blockDim.x + threadIdx.x;   // f = e*B + b
    int e = f >> 1, b = f & 1;
    unsigned t0 = 0u, t1 = (unsigned)f;
    threefry2x32_dev(0u, 42u, t0, t1);
    float g = bits_to_gumbel(t0 ^ t1);
    float l = logits[(size_t)b * EE + e];
    float a = (l + g) / 0.1f;
    av[f] = a;
    int n2 = src[e] * BB + b;
    atomicMax(&mxh[n2], enc_f(a));
    atomicMax(&mxs[n2], enc_f(l));
}

__global__ void sum_kernel(const float* __restrict__ logits, const float* __restrict__ av,
                           const int* __restrict__ src,
                           const unsigned* __restrict__ mxh, const unsigned* __restrict__ mxs,
                           float* __restrict__ sh, float* __restrict__ ss) {
    int f = blockIdx.x * blockDim.x + threadIdx.x;
    int e = f >> 1, b = f & 1;
    int n2 = src[e] * BB + b;
    atomicAdd(&sh[n2], expf(av[f] - dec_f(mxh[n2])));
    atomicAdd(&ss[n2], expf(logits[(size_t)b * EE + e] - dec_f(mxs[n2])));
}

__global__ void scatter_kernel(const float* __restrict__ h,
                               const int* __restrict__ tgt, const int* __restrict__ src,
                               const float* __restrict__ logits, const float* __restrict__ av,
                               const unsigned* __restrict__ mxh, const unsigned* __restrict__ mxs,
                               const float* __restrict__ sh, const float* __restrict__ ss,
                               float* __restrict__ out) {
    int e = blockIdx.x;
    int j = threadIdx.x;
    int s = src[e], t = tgt[e];
    #pragma unroll
    for (int b = 0; b < BB; b++) {
        int n2 = s * BB + b;
        float a = av[e * BB + b];
        float l = logits[(size_t)b * EE + e];
        float w = (expf(a - dec_f(mxh[n2])) / sh[n2]) * (expf(l - dec_f(mxs[n2])) / ss[n2]);
        float hv = h[((size_t)b * NN + s) * HH + j];
        atomicAdd(&out[((size_t)b * NN + t) * HH + j], hv * w);
    }
}

// ---------------- host orchestration ---------------------------------------------
extern "C" void kernel_launch(void* const* d_in, const int* in_sizes, int n_in,
                              void* d_out, int out_size) {
    static const int map_ins[20]   = {0,1,2,3,4,5,6,7,8,9,10,11,12,13,14,15,16,17,18,19};
    static const int map_alpha[20] = {10,9,17,13,6,2,16,12,5,1,19,15,8,4,18,14,7,3,11,0};
    const int* mp = (in_sizes[0] == BB * NN * HH) ? map_ins : map_alpha;

    const float* h   = (const float*)d_in[mp[0]];
    const int* ei    = (const int*)d_in[mp[1]];
    const int* tgt   = ei;
    const int* src   = ei + EE;
    const float* wih0f = (const float*)d_in[mp[2]];
    const float* whh0f = (const float*)d_in[mp[3]];
    const float* bih0f = (const float*)d_in[mp[4]];
    const float* bhh0f = (const float*)d_in[mp[5]];
    const float* wih0b = (const float*)d_in[mp[6]];
    const float* whh0b = (const float*)d_in[mp[7]];
    const float* bih0b = (const float*)d_in[mp[8]];
    const float* bhh0b = (const float*)d_in[mp[9]];
    const float* wih1f = (const float*)d_in[mp[10]];
    const float* bih1f = (const float*)d_in[mp[12]];
    const float* bhh1f = (const float*)d_in[mp[13]];
    const float* wih1b = (const float*)d_in[mp[14]];
    const float* whh1b = (const float*)d_in[mp[15]];
    const float* bih1b = (const float*)d_in[mp[16]];
    const float* bhh1b = (const float*)d_in[mp[17]];
    const float* wcon  = (const float*)d_in[mp[18]];
    const float* bcon  = (const float*)d_in[mp[19]];
    float* out = (float*)d_out;

    float *giA, *giB, *gh, *y0, *y1, *hhb, *hb1, *logits, *av, *sh, *ss;
    unsigned *mxh, *mxs;
    __nv_bfloat16 *x0h, *x0l, *x1h, *x1l, *y0h, *y0l, *y1h, *y1l, *hb1h, *hb1l;
    __nv_bfloat16 *wpkh, *wpkl;
    cudaGetSymbolAddress((void**)&giA, g_giA);
    cudaGetSymbolAddress((void**)&giB, g_giB);
    cudaGetSymbolAddress((void**)&gh, g_gh);
    cudaGetSymbolAddress((void**)&y0, g_y0);
    cudaGetSymbolAddress((void**)&y1, g_y1);
    cudaGetSymbolAddress((void**)&hhb, g_hh);
    cudaGetSymbolAddress((void**)&hb1, g_hb1);
    cudaGetSymbolAddress((void**)&logits, g_logits);
    cudaGetSymbolAddress((void**)&av, g_av);
    cudaGetSymbolAddress((void**)&mxh, g_mxh);
    cudaGetSymbolAddress((void**)&mxs, g_mxs);
    cudaGetSymbolAddress((void**)&sh, g_sh);
    cudaGetSymbolAddress((void**)&ss, g_ss);
    cudaGetSymbolAddress((void**)&x0h, g_x0h);
    cudaGetSymbolAddress((void**)&x0l, g_x0l);
    cudaGetSymbolAddress((void**)&x1h, g_x1h);
    cudaGetSymbolAddress((void**)&x1l, g_x1l);
    cudaGetSymbolAddress((void**)&y0h, g_y0h);
    cudaGetSymbolAddress((void**)&y0l, g_y0l);
    cudaGetSymbolAddress((void**)&y1h, g_y1h);
    cudaGetSymbolAddress((void**)&y1l, g_y1l);
    cudaGetSymbolAddress((void**)&hb1h, g_hb1h);
    cudaGetSymbolAddress((void**)&hb1l, g_hb1l);
    cudaGetSymbolAddress((void**)&wpkh, g_wpk_h);
    cudaGetSymbolAddress((void**)&wpkl, g_wpk_l);

    cudaFuncSetAttribute(sgemm_mma, cudaFuncAttributeMaxDynamicSharedMemorySize, PSMEM);

    __nv_bfloat16 *pw0  = wpkh + 0,      *pw0_l  = wpkl + 0;        // [wih0f|wih0b]
    __nv_bfloat16 *ph0f = wpkh + 98304,  *ph0f_l = wpkl + 98304;    // whh0f
    __nv_bfloat16 *ph0b = wpkh + 147456, *ph0b_l = wpkl + 147456;   // whh0b
    __nv_bfloat16 *ph1b = wpkh + 196608, *ph1b_l = wpkl + 196608;   // whh1b
    __nv_bfloat16 *pw1  = wpkh + 245760, *pw1_l  = wpkl + 245760;   // [wih1f|wih1b]
    __nv_bfloat16 *pw1b = wpkh + 344064, *pw1b_l = wpkl + 344064;   // wih1b

    pack_all<<<(WPK_TOTAL + 255) / 256, 256>>>(wih0f, wih0b, whh0f, whh0b, whh1b,
                                               wih1f, wih1b, wpkh, wpkl);

    dim3 grid6(6, 2000), grid3(3, 2000);
    const long long PW_BLOCKS = ((long long)MM * 128) / 256;

    gather_kernel<<<(MM * 32) / 256, 256>>>((const float4*)h, tgt, src,
                                            x0h, x0l, x1h, x1l);

    // ---- batched input GEMMs: gi = x @ [W_f | W_b]^T  (768 cols) ----
    sgemm_mma<<<grid6, 256, PSMEM>>>(x0h, x0l, 128, pw0, pw0_l, 4, giA, 768);
    sgemm_mma<<<grid6, 256, PSMEM>>>(x1h, x1l, 128, pw0, pw0_l, 4, giB, 768);

    // f0 = cell_f(x0, 0)   b1 = cell_b(x1, 0)   [one dual launch]
    gru_pointwise_dual<<<2 * PW_BLOCKS, 256>>>(PW_BLOCKS,
        giA, 768, bih0f, bhh0f, y0, 256, y0h, y0l, 256,
        giB + 384, 768, bih0b, bhh0b, y1 + 128, 256, y1h + 128, y1l + 128, 256);

    // f1 = cell_f(x1, f0)  (fp32 out unused downstream -> null)
    sgemm_mma<<<grid3, 256, PSMEM>>>(y0h, y0l, 256, ph0f, ph0f_l, 4, gh, 384);
    gru_pointwise<<<PW_BLOCKS, 256>>>(giB, 768, gh, y0, 256, bih0f, bhh0f,
                                      nullptr, 0, y1h, y1l, 256);

    // b0 = cell_b(x0, b1)  (fp32 out unused downstream -> null)
    sgemm_mma<<<grid3, 256, PSMEM>>>(y1h + 128, y1l + 128, 256, ph0b, ph0b_l, 4, gh, 384);
    gru_pointwise<<<PW_BLOCKS, 256>>>(giA + 384, 768, gh, y1 + 128, 256, bih0b, bhh0b,
                                      nullptr, 0, y0h + 128, y0l + 128, 256);

    // ---- layer 1: giA = y0 @ [W1f|W1b], giB = y1 @ W1b ----
    sgemm_mma<<<grid6, 256, PSMEM>>>(y0h, y0l, 256, pw1, pw1_l, 8, giA, 768);
    sgemm_mma<<<grid3, 256, PSMEM>>>(y1h, y1l, 256, pw1b, pw1b_l, 8, giB, 384);

    // f0' = cell_f1(y0, 0)   b1' = cell_b1(y1, 0)   [one dual launch]
    gru_pointwise_dual<<<2 * PW_BLOCKS, 256>>>(PW_BLOCKS,
        giA, 768, bih1f, bhh1f, hhb, 256, nullptr, nullptr, 0,
        giB, 384, bih1b, bhh1b, hb1, 128, hb1h, hb1l, 128);

    // b0' = cell_b1(y0, b1')
    sgemm_mma<<<grid3, 256, PSMEM>>>(hb1h, hb1l, 128, ph1b, ph1b_l, 4, gh, 384);
    gru_pointwise<<<PW_BLOCKS, 256>>>(giA + 384, 768, gh, hb1, 128, bih1b, bhh1b,
                                      hhb + 128, 256, nullptr, nullptr, 0);

    // ---- logits, segment softmaxes (gumbel fused into prep), weighted scatter ----
    logits_kernel<<<(MM * 32) / 256, 256>>>(hhb, wcon, bcon, logits);
    init_kernel<<<(BB * NN * HH + 255) / 256, 256>>>(out, mxh, mxs, sh, ss);
    prep_kernel<<<MM / 256, 256>>>(logits, src, av, mxh, mxs);
    sum_kernel<<<MM / 256, 256>>>(logits, av, src, mxh, mxs, sh, ss);
    scatter_kernel<<<EE, 128>>>(h, tgt, src, logits, av, mxh, mxs, sh, ss, out);
}

// round 15
// speedup vs baseline: 1.0525x; 1.0525x over previous
#include <cuda_runtime.h>
#include <cuda_bf16.h>
#include <math.h>
#include <stdint.h>

// Problem constants
#define BB 2
#define NN 10000
#define HH 128
#define EE 128000
#define MM (BB*EE)          // 256000 rows
#define GDIM 384            // 3*H

// ---------------- scratch (device globals; no runtime allocation) -------------
__device__ float g_giA[(size_t)MM*768];
__device__ float g_giB[(size_t)MM*768];
__device__ float g_gh[(size_t)MM*384];
__device__ float g_y0[(size_t)MM*256];
__device__ float g_y1[(size_t)MM*256];
__device__ float g_hh[(size_t)MM*256];
__device__ float g_hb1[(size_t)MM*128];
__device__ float g_logits[MM];
__device__ float g_av[MM];
__device__ unsigned g_mxh[NN*BB];
__device__ unsigned g_mxs[NN*BB];
__device__ float g_sh[NN*BB];
__device__ float g_ss[NN*BB];

// bf16 hi/lo activation buffers
__device__ __nv_bfloat16 g_x0h[(size_t)MM*128], g_x0l[(size_t)MM*128];
__device__ __nv_bfloat16 g_x1h[(size_t)MM*128], g_x1l[(size_t)MM*128];
__device__ __nv_bfloat16 g_y0h[(size_t)MM*256], g_y0l[(size_t)MM*256];
__device__ __nv_bfloat16 g_y1h[(size_t)MM*256], g_y1l[(size_t)MM*256];
__device__ __nv_bfloat16 g_hb1h[(size_t)MM*128], g_hb1l[(size_t)MM*128];

// packed pre-split weights: layout [cb][kc][r(128)][c(32)]
// regions: wih0f 0 | wih0b 49152 | whh0f 98304 | whh0b 147456 |
//          whh1b 196608 | wih1f 245760 (K=256) | wih1b 344064 (K=256)
#define WPK_TOTAL 442368
__device__ __nv_bfloat16 g_wpk_h[WPK_TOTAL];
__device__ __nv_bfloat16 g_wpk_l[WPK_TOTAL];

// ---------------- helpers -----------------------------------------------------
__device__ __forceinline__ unsigned enc_f(float x) {
    unsigned u = __float_as_uint(x);
    return (u & 0x80000000u) ? ~u : (u | 0x80000000u);
}
__device__ __forceinline__ float dec_f(unsigned v) {
    return (v & 0x80000000u) ? __uint_as_float(v ^ 0x80000000u) : __uint_as_float(~v);
}
#define ENC_NEG_INF 0x007FFFFFu

__device__ __forceinline__ float sigmoidf_(float x) { return 1.0f / (1.0f + expf(-x)); }

__device__ __forceinline__ uint32_t smem_u32(const void* p) {
    uint32_t a;
    asm("{ .reg .u64 t; cvta.to.shared.u64 t, %1; cvt.u32.u64 %0, t; }" : "=r"(a) : "l"(p));
    return a;
}

#define LDMX4(r0, r1, r2, r3, addr) \
    asm volatile("ldmatrix.sync.aligned.m8n8.x4.shared.b16 {%0,%1,%2,%3}, [%4];" \
                 : "=r"(r0), "=r"(r1), "=r"(r2), "=r"(r3) : "r"(addr))

#define MMA_BF16(c, a0, a1, a2, a3, b0, b1) \
    asm volatile("mma.sync.aligned.m16n8k16.row.col.f32.bf16.bf16.f32 " \
                 "{%0,%1,%2,%3}, {%4,%5,%6,%7}, {%8,%9}, {%0,%1,%2,%3};" \
                 : "+f"((c)[0]), "+f"((c)[1]), "+f"((c)[2]), "+f"((c)[3]) \
                 : "r"(a0), "r"(a1), "r"(a2), "r"(a3), "r"(b0), "r"(b1))

#define CPA16(dst, src) \
    asm volatile("cp.async.cg.shared.global [%0], [%1], 16;" :: "r"(dst), "l"(src))
#define CPA_COMMIT() asm volatile("cp.async.commit_group;" ::: "memory")
#define CPA_WAIT1() asm volatile("cp.async.wait_group 1;" ::: "memory")

__device__ __forceinline__ void split_bf16(float x, __nv_bfloat16& hi, __nv_bfloat16& lo) {
    hi = __float2bfloat16_rn(x);
    lo = __float2bfloat16_rn(x - __bfloat162float(hi));
}

// ---------------- weight pre-split/pack: ALL weights in one launch ---------------
__global__ void pack_all(const float* __restrict__ wih0f, const float* __restrict__ wih0b,
                         const float* __restrict__ whh0f, const float* __restrict__ whh0b,
                         const float* __restrict__ whh1b,
                         const float* __restrict__ wih1f, const float* __restrict__ wih1b,
                         __nv_bfloat16* __restrict__ outh,
                         __nv_bfloat16* __restrict__ outl) {
    int idx = blockIdx.x * blockDim.x + threadIdx.x;
    if (idx >= WPK_TOTAL) return;
    const float* W; int base, K;
    if      (idx < 49152)  { W = wih0f; base = 0;      K = 128; }
    else if (idx < 98304)  { W = wih0b; base = 49152;  K = 128; }
    else if (idx < 147456) { W = whh0f; base = 98304;  K = 128; }
    else if (idx < 196608) { W = whh0b; base = 147456; K = 128; }
    else if (idx < 245760) { W = whh1b; base = 196608; K = 128; }
    else if (idx < 344064) { W = wih1f; base = 245760; K = 256; }
    else                   { W = wih1b; base = 344064; K = 256; }
    int li = idx - base;
    int nkc = K >> 5;
    int c = li & 31;
    int r = (li >> 5) & 127;
    int kcb = li >> 12;
    int kc = kcb % nkc, cb = kcb / nkc;
    float v = W[(size_t)(cb * 128 + r) * K + kc * 32 + c];
    __nv_bfloat16 hi, lo; split_bf16(v, hi, lo);
    outh[idx] = hi; outl[idx] = lo;
}

// ---------------- gather (writes bf16 hi/lo) ------------------------------------
__global__ void gather_kernel(const float4* __restrict__ h,
                              const int* __restrict__ tgt,
                              const int* __restrict__ src,
                              __nv_bfloat16* __restrict__ x0h, __nv_bfloat16* __restrict__ x0l,
                              __nv_bfloat16* __restrict__ x1h, __nv_bfloat16* __restrict__ x1l) {
    long long idx = (long long)blockIdx.x * blockDim.x + threadIdx.x;
    int q = (int)(idx & 31);
    long long be = idx >> 5;
    int e = (int)(be % EE);
    int b = (int)(be / EE);
    int t = tgt[e], s = src[e];
    float4 vt = h[((long long)b * NN + t) * 32 + q];
    float4 vs = h[((long long)b * NN + s) * 32 + q];
    __nv_bfloat16 hh_[4], ll_[4];
    long long o = be * 128 + q * 4;
    split_bf16(vt.x, hh_[0], ll_[0]); split_bf16(vt.y, hh_[1], ll_[1]);
    split_bf16(vt.z, hh_[2], ll_[2]); split_bf16(vt.w, hh_[3], ll_[3]);
    *(ulonglong1*)(x0h + o) = *(ulonglong1*)hh_;
    *(ulonglong1*)(x0l + o) = *(ulonglong1*)ll_;
    split_bf16(vs.x, hh_[0], ll_[0]); split_bf16(vs.y, hh_[1], ll_[1]);
    split_bf16(vs.z, hh_[2], ll_[2]); split_bf16(vs.w, hh_[3], ll_[3]);
    *(ulonglong1*)(x1h + o) = *(ulonglong1*)hh_;
    *(ulonglong1*)(x1l + o) = *(ulonglong1*)ll_;
}

// ---------------- bf16x3 HMMA GEMM, 2-stage cp.async, 2 CTAs/SM ------------------
#define SBF 40
#define TILE_B (128 * SBF * 2)
#define STAGE_B (4 * TILE_B)     // 40960
#define PSMEM (2 * STAGE_B)      // 81920

__global__ void __launch_bounds__(256, 2) sgemm_mma(
        const __nv_bfloat16* __restrict__ Ah, const __nv_bfloat16* __restrict__ Al,
        int lda,
        const __nv_bfloat16* __restrict__ Wh, const __nv_bfloat16* __restrict__ Wl,
        int nkc,
        float* __restrict__ C, int ldc) {
    extern __shared__ __align__(16) char smem[];
    uint32_t sb = smem_u32(smem);

    int tid = threadIdx.x;
    int lane = tid & 31;
    int wid = tid >> 5;
    int warp_m = wid & 3;
    int warp_n = wid >> 2;
    int rowBlk = blockIdx.y * 128;
    int cb = blockIdx.x;

    float c[2][8][4];
    #pragma unroll
    for (int i = 0; i < 2; i++)
        #pragma unroll
        for (int j = 0; j < 8; j++)
            #pragma unroll
            for (int q = 0; q < 4; q++) c[i][j][q] = 0.0f;

    auto issue = [&](int kc, int s) {
        #pragma unroll
        for (int q = 0; q < 8; q++) {
            int id = tid + q * 256;
            int tile = id >> 9;
            int rem = id & 511;
            int r = rem >> 2, c16 = rem & 3;
            uint32_t dst = sb + s * STAGE_B + tile * TILE_B + r * (SBF * 2) + c16 * 16;
            const __nv_bfloat16* src;
            if (tile == 0)
                src = Ah + (size_t)(rowBlk + r) * lda + kc * 32 + c16 * 8;
            else if (tile == 1)
                src = Al + (size_t)(rowBlk + r) * lda + kc * 32 + c16 * 8;
            else if (tile == 2)
                src = Wh + ((size_t)(cb * nkc + kc) << 12) + r * 32 + c16 * 8;
            else
                src = Wl + ((size_t)(cb * nkc + kc) << 12) + r * 32 + c16 * 8;
            CPA16(dst, src);
        }
    };

    int a_r = lane & 15, a_c = (lane >> 4) << 3;
    int b_r = (lane & 7) + ((lane >> 4) << 3);
    int b_c = ((lane >> 3) & 1) << 3;

    issue(0, 0);
    CPA_COMMIT();

    for (int kc = 0; kc < nkc; kc++) {
        if (kc + 1 < nkc) issue(kc + 1, (kc + 1) & 1);
        CPA_COMMIT();
        CPA_WAIT1();
        __syncthreads();

        uint32_t st = sb + (kc & 1) * STAGE_B;
        uint32_t uAh = st, uAl = st + TILE_B, uWh = st + 2 * TILE_B, uWl = st + 3 * TILE_B;

        #pragma unroll
        for (int ks = 0; ks < 2; ks++) {
            uint32_t ah[2][4], al[2][4];
            #pragma unroll
            for (int mt = 0; mt < 2; mt++) {
                uint32_t eoff = (uint32_t)((warp_m * 32 + mt * 16 + a_r) * SBF
                                           + ks * 16 + a_c) * 2;
                LDMX4(ah[mt][0], ah[mt][1], ah[mt][2], ah[mt][3], uAh + eoff);
                LDMX4(al[mt][0], al[mt][1], al[mt][2], al[mt][3], uAl + eoff);
            }
            #pragma unroll
            for (int np = 0; np < 4; np++) {
                uint32_t bh[4], bl[4];
                uint32_t eoff = (uint32_t)((warp_n * 64 + np * 16 + b_r) * SBF
                                           + ks * 16 + b_c) * 2;
                LDMX4(bh[0], bh[1], bh[2], bh[3], uWh + eoff);
                LDMX4(bl[0], bl[1], bl[2], bl[3], uWl + eoff);
                #pragma unroll
                for (int mt = 0; mt < 2; mt++) {
                    float* c0 = c[mt][np * 2];
                    float* c1 = c[mt][np * 2 + 1];
                    MMA_BF16(c0, ah[mt][0], ah[mt][1], ah[mt][2], ah[mt][3], bh[0], bh[1]);
                    MMA_BF16(c0, ah[mt][0], ah[mt][1], ah[mt][2], ah[mt][3], bl[0], bl[1]);
                    MMA_BF16(c0, al[mt][0], al[mt][1], al[mt][2], al[mt][3], bh[0], bh[1]);
                    MMA_BF16(c1, ah[mt][0], ah[mt][1], ah[mt][2], ah[mt][3], bh[2], bh[3]);
                    MMA_BF16(c1, ah[mt][0], ah[mt][1], ah[mt][2], ah[mt][3], bl[2], bl[3]);
                    MMA_BF16(c1, al[mt][0], al[mt][1], al[mt][2], al[mt][3], bh[2], bh[3]);
                }
            }
        }
        __syncthreads();
    }

    int colBlk = cb * 128;
    #pragma unroll
    for (int mt = 0; mt < 2; mt++) {
        int r = rowBlk + warp_m * 32 + mt * 16 + (lane >> 2);
        #pragma unroll
        for (int nt = 0; nt < 8; nt++) {
            int col = colBlk + warp_n * 64 + nt * 8 + (lane & 3) * 2;
            *(float2*)(C + (size_t)r * ldc + col) =
                make_float2(c[mt][nt][0], c[mt][nt][1]);
            *(float2*)(C + (size_t)(r + 8) * ldc + col) =
                make_float2(c[mt][nt][2], c[mt][nt][3]);
        }
    }
}

// ---------------- GRU pointwise (nullable fp32 out; optional bf16 hi/lo) ---------
__global__ void gru_pointwise(const float* __restrict__ gi, int gi_stride,
                              const float* __restrict__ gh,
                              const float* __restrict__ hp, int hp_stride,
                              const float* __restrict__ b_ih,
                              const float* __restrict__ b_hh,
                              float* __restrict__ out, int out_stride,
                              __nv_bfloat16* __restrict__ outh,
                              __nv_bfloat16* __restrict__ outl, int bf_stride) {
    long long idx = (long long)blockIdx.x * blockDim.x + threadIdx.x;
    int j = (int)(idx & 127);
    long long m = idx >> 7;
    const float* gir = gi + m * (long long)gi_stride;
    float ir = gir[j]        + b_ih[j];
    float iz = gir[128 + j]  + b_ih[128 + j];
    float in_ = gir[256 + j] + b_ih[256 + j];
    float hr, hz, hn;
    if (gh) {
        const float* ghr = gh + m * GDIM;
        hr = ghr[j]       + b_hh[j];
        hz = ghr[128 + j] + b_hh[128 + j];
        hn = ghr[256 + j] + b_hh[256 + j];
    } else {
        hr = b_hh[j]; hz = b_hh[128 + j]; hn = b_hh[256 + j];
    }
    float r = sigmoidf_(ir + hr);
    float z = sigmoidf_(iz + hz);
    float n = tanhf(in_ + r * hn);
    float hv = hp ? hp[m * (long long)hp_stride + j] : 0.0f;
    float o = (1.0f - z) * n + z * hv;
    if (out) out[m * (long long)out_stride + j] = o;
    if (outh) {
        __nv_bfloat16 hi, lo; split_bf16(o, hi, lo);
        outh[m * (long long)bf_stride + j] = hi;
        outl[m * (long long)bf_stride + j] = lo;
    }
}

// ---------------- logits ---------------------------------------------------------
__global__ void logits_kernel(const float* __restrict__ hh,
                              const float* __restrict__ w_con,
                              const float* __restrict__ b_con,
                              float* __restrict__ logits) {
    long long gth = (long long)blockIdx.x * blockDim.x + threadIdx.x;
    long long warp = gth >> 5;
    int lane = (int)(gth & 31);
    const float* row = hh + warp * 256;
    float s = 0.0f;
    #pragma unroll
    for (int k = 0; k < 8; k++) s = fmaf(row[lane + k * 32], w_con[lane + k * 32], s);
    #pragma unroll
    for (int o = 16; o > 0; o >>= 1) s += __shfl_xor_sync(0xFFFFFFFFu, s, o);
    if (lane == 0) {
        float x = s + b_con[0];
        logits[warp] = 0.5f * x * (1.0f + erff(x * 0.70710678118654752440f));
    }
}

// ---------------- JAX threefry2x32 gumbel, partitionable mode -------------------
__device__ __forceinline__ void threefry2x32_dev(unsigned k0, unsigned k1,
                                                 unsigned& x0, unsigned& x1) {
    unsigned ks2 = k0 ^ k1 ^ 0x1BD11BDAu;
    x0 += k0; x1 += k1;
#define TFR(r) { x0 += x1; x1 = (x1 << (r)) | (x1 >> (32 - (r))); x1 ^= x0; }
#define TFG(a, b, c, d, A0, A1, INC) TFR(a) TFR(b) TFR(c) TFR(d) x0 += (A0); x1 += (A1) + (INC);
    TFG(13, 15, 26, 6,  k1,  ks2, 1u)
    TFG(17, 29, 16, 24, ks2, k0,  2u)
    TFG(13, 15, 26, 6,  k0,  k1,  3u)
    TFG(17, 29, 16, 24, k1,  ks2, 4u)
    TFG(13, 15, 26, 6,  ks2, k0,  5u)
#undef TFR
#undef TFG
}

__device__ __forceinline__ float bits_to_gumbel(unsigned bits) {
    float u = __uint_as_float((bits >> 9) | 0x3f800000u) - 1.0f;
    float v = fmaxf(u, 1.175494350822287508e-38f);
    return -logf(-logf(v));
}

// ---------------- init / segment softmax / scatter -------------------------------
__global__ void init_kernel(float* __restrict__ out,
                            unsigned* __restrict__ mxh, unsigned* __restrict__ mxs,
                            float* __restrict__ sh, float* __restrict__ ss) {
    int i = blockIdx.x * blockDim.x + threadIdx.x;
    if (i < BB * NN * HH) out[i] = 0.0f;
    if (i < NN * BB) { mxh[i] = ENC_NEG_INF; mxs[i] = ENC_NEG_INF; sh[i] = 0.0f; ss[i] = 0.0f; }
}

__global__ void prep_kernel(const float* __restrict__ logits,
                            const int* __restrict__ src,
                            float* __restrict__ av,
                            unsigned* __restrict__ mxh, unsigned* __restrict__ mxs) {
    int f = blockIdx.x * blockDim.x + threadIdx.x;   // f = e*B + b
    int e = f >> 1, b = f & 1;
    unsigned t0 = 0u, t1 = (unsigned)f;
    threefry2x32_dev(0u, 42u, t0, t1);
    float g = bits_to_gumbel(t0 ^ t1);
    float l = logits[(size_t)b * EE + e];
    float a = (l + g) / 0.1f;
    av[f] = a;
    int n2 = src[e] * BB + b;
    atomicMax(&mxh[n2], enc_f(a));
    atomicMax(&mxs[n2], enc_f(l));
}

__global__ void sum_kernel(const float* __restrict__ logits, const float* __restrict__ av,
                           const int* __restrict__ src,
                           const unsigned* __restrict__ mxh, const unsigned* __restrict__ mxs,
                           float* __restrict__ sh, float* __restrict__ ss) {
    int f = blockIdx.x * blockDim.x + threadIdx.x;
    int e = f >> 1, b = f & 1;
    int n2 = src[e] * BB + b;
    atomicAdd(&sh[n2], expf(av[f] - dec_f(mxh[n2])));
    atomicAdd(&ss[n2], expf(logits[(size_t)b * EE + e] - dec_f(mxs[n2])));
}

__global__ void scatter_kernel(const float* __restrict__ h,
                               const int* __restrict__ tgt, const int* __restrict__ src,
                               const float* __restrict__ logits, const float* __restrict__ av,
                               const unsigned* __restrict__ mxh, const unsigned* __restrict__ mxs,
                               const float* __restrict__ sh, const float* __restrict__ ss,
                               float* __restrict__ out) {
    int e = blockIdx.x;
    int j = threadIdx.x;
    int s = src[e], t = tgt[e];
    #pragma unroll
    for (int b = 0; b < BB; b++) {
        int n2 = s * BB + b;
        float a = av[e * BB + b];
        float l = logits[(size_t)b * EE + e];
        float w = (expf(a - dec_f(mxh[n2])) / sh[n2]) * (expf(l - dec_f(mxs[n2])) / ss[n2]);
        float hv = h[((size_t)b * NN + s) * HH + j];
        atomicAdd(&out[((size_t)b * NN + t) * HH + j], hv * w);
    }
}

// ---------------- host orchestration ---------------------------------------------
extern "C" void kernel_launch(void* const* d_in, const int* in_sizes, int n_in,
                              void* d_out, int out_size) {
    static const int map_ins[20]   = {0,1,2,3,4,5,6,7,8,9,10,11,12,13,14,15,16,17,18,19};
    static const int map_alpha[20] = {10,9,17,13,6,2,16,12,5,1,19,15,8,4,18,14,7,3,11,0};
    const int* mp = (in_sizes[0] == BB * NN * HH) ? map_ins : map_alpha;

    const float* h   = (const float*)d_in[mp[0]];
    const int* ei    = (const int*)d_in[mp[1]];
    const int* tgt   = ei;
    const int* src   = ei + EE;
    const float* wih0f = (const float*)d_in[mp[2]];
    const float* whh0f = (const float*)d_in[mp[3]];
    const float* bih0f = (const float*)d_in[mp[4]];
    const float* bhh0f = (const float*)d_in[mp[5]];
    const float* wih0b = (const float*)d_in[mp[6]];
    const float* whh0b = (const float*)d_in[mp[7]];
    const float* bih0b = (const float*)d_in[mp[8]];
    const float* bhh0b = (const float*)d_in[mp[9]];
    const float* wih1f = (const float*)d_in[mp[10]];
    const float* bih1f = (const float*)d_in[mp[12]];
    const float* bhh1f = (const float*)d_in[mp[13]];
    const float* wih1b = (const float*)d_in[mp[14]];
    const float* whh1b = (const float*)d_in[mp[15]];
    const float* bih1b = (const float*)d_in[mp[16]];
    const float* bhh1b = (const float*)d_in[mp[17]];
    const float* wcon  = (const float*)d_in[mp[18]];
    const float* bcon  = (const float*)d_in[mp[19]];
    float* out = (float*)d_out;

    float *giA, *giB, *gh, *y0, *y1, *hhb, *hb1, *logits, *av, *sh, *ss;
    unsigned *mxh, *mxs;
    __nv_bfloat16 *x0h, *x0l, *x1h, *x1l, *y0h, *y0l, *y1h, *y1l, *hb1h, *hb1l;
    __nv_bfloat16 *wpkh, *wpkl;
    cudaGetSymbolAddress((void**)&giA, g_giA);
    cudaGetSymbolAddress((void**)&giB, g_giB);
    cudaGetSymbolAddress((void**)&gh, g_gh);
    cudaGetSymbolAddress((void**)&y0, g_y0);
    cudaGetSymbolAddress((void**)&y1, g_y1);
    cudaGetSymbolAddress((void**)&hhb, g_hh);
    cudaGetSymbolAddress((void**)&hb1, g_hb1);
    cudaGetSymbolAddress((void**)&logits, g_logits);
    cudaGetSymbolAddress((void**)&av, g_av);
    cudaGetSymbolAddress((void**)&mxh, g_mxh);
    cudaGetSymbolAddress((void**)&mxs, g_mxs);
    cudaGetSymbolAddress((void**)&sh, g_sh);
    cudaGetSymbolAddress((void**)&ss, g_ss);
    cudaGetSymbolAddress((void**)&x0h, g_x0h);
    cudaGetSymbolAddress((void**)&x0l, g_x0l);
    cudaGetSymbolAddress((void**)&x1h, g_x1h);
    cudaGetSymbolAddress((void**)&x1l, g_x1l);
    cudaGetSymbolAddress((void**)&y0h, g_y0h);
    cudaGetSymbolAddress((void**)&y0l, g_y0l);
    cudaGetSymbolAddress((void**)&y1h, g_y1h);
    cudaGetSymbolAddress((void**)&y1l, g_y1l);
    cudaGetSymbolAddress((void**)&hb1h, g_hb1h);
    cudaGetSymbolAddress((void**)&hb1l, g_hb1l);
    cudaGetSymbolAddress((void**)&wpkh, g_wpk_h);
    cudaGetSymbolAddress((void**)&wpkl, g_wpk_l);

    cudaFuncSetAttribute(sgemm_mma, cudaFuncAttributeMaxDynamicSharedMemorySize, PSMEM);

    __nv_bfloat16 *pw0  = wpkh + 0,      *pw0_l  = wpkl + 0;        // [wih0f|wih0b]
    __nv_bfloat16 *ph0f = wpkh + 98304,  *ph0f_l = wpkl + 98304;    // whh0f
    __nv_bfloat16 *ph0b = wpkh + 147456, *ph0b_l = wpkl + 147456;   // whh0b
    __nv_bfloat16 *ph1b = wpkh + 196608, *ph1b_l = wpkl + 196608;   // whh1b
    __nv_bfloat16 *pw1  = wpkh + 245760, *pw1_l  = wpkl + 245760;   // [wih1f|wih1b]
    __nv_bfloat16 *pw1b = wpkh + 344064, *pw1b_l = wpkl + 344064;   // wih1b

    pack_all<<<(WPK_TOTAL + 255) / 256, 256>>>(wih0f, wih0b, whh0f, whh0b, whh1b,
                                               wih1f, wih1b, wpkh, wpkl);

    dim3 grid6(6, 2000), grid3(3, 2000);
    const int PW_BLOCKS = (MM * 128) / 256;

    gather_kernel<<<(MM * 32) / 256, 256>>>((const float4*)h, tgt, src,
                                            x0h, x0l, x1h, x1l);

    // ---- batched input GEMMs: gi = x @ [W_f | W_b]^T  (768 cols) ----
    sgemm_mma<<<grid6, 256, PSMEM>>>(x0h, x0l, 128, pw0, pw0_l, 4, giA, 768);
    sgemm_mma<<<grid6, 256, PSMEM>>>(x1h, x1l, 128, pw0, pw0_l, 4, giB, 768);

    // f0 = cell_f(x0, 0)   b1 = cell_b(x1, 0)
    gru_pointwise<<<PW_BLOCKS, 256>>>(giA, 768, nullptr, nullptr, 0, bih0f, bhh0f,
                                      y0, 256, y0h, y0l, 256);
    gru_pointwise<<<PW_BLOCKS, 256>>>(giB + 384, 768, nullptr, nullptr, 0, bih0b, bhh0b,
                                      y1 + 128, 256, y1h + 128, y1l + 128, 256);

    // f1 = cell_f(x1, f0)  (fp32 out unused downstream -> null)
    sgemm_mma<<<grid3, 256, PSMEM>>>(y0h, y0l, 256, ph0f, ph0f_l, 4, gh, 384);
    gru_pointwise<<<PW_BLOCKS, 256>>>(giB, 768, gh, y0, 256, bih0f, bhh0f,
                                      nullptr, 0, y1h, y1l, 256);

    // b0 = cell_b(x0, b1)  (fp32 out unused downstream -> null)
    sgemm_mma<<<grid3, 256, PSMEM>>>(y1h + 128, y1l + 128, 256, ph0b, ph0b_l, 4, gh, 384);
    gru_pointwise<<<PW_BLOCKS, 256>>>(giA + 384, 768, gh, y1 + 128, 256, bih0b, bhh0b,
                                      nullptr, 0, y0h + 128, y0l + 128, 256);

    // ---- layer 1: giA = y0 @ [W1f|W1b], giB = y1 @ W1b ----
    sgemm_mma<<<grid6, 256, PSMEM>>>(y0h, y0l, 256, pw1, pw1_l, 8, giA, 768);
    sgemm_mma<<<grid3, 256, PSMEM>>>(y1h, y1l, 256, pw1b, pw1b_l, 8, giB, 384);

    // f0' = cell_f1(y0, 0)   b1' = cell_b1(y1, 0)
    gru_pointwise<<<PW_BLOCKS, 256>>>(giA, 768, nullptr, nullptr, 0, bih1f, bhh1f,
                                      hhb, 256, nullptr, nullptr, 0);
    gru_pointwise<<<PW_BLOCKS, 256>>>(giB, 384, nullptr, nullptr, 0, bih1b, bhh1b,
                                      hb1, 128, hb1h, hb1l, 128);

    // b0' = cell_b1(y0, b1')
    sgemm_mma<<<grid3, 256, PSMEM>>>(hb1h, hb1l, 128, ph1b, ph1b_l, 4, gh, 384);
    gru_pointwise<<<PW_BLOCKS, 256>>>(giA + 384, 768, gh, hb1, 128, bih1b, bhh1b,
                                      hhb + 128, 256, nullptr, nullptr, 0);

    // ---- logits, segment softmaxes (gumbel fused into prep), weighted scatter ----
    logits_kernel<<<(MM * 32) / 256, 256>>>(hhb, wcon, bcon, logits);
    init_kernel<<<(BB * NN * HH + 255) / 256, 256>>>(out, mxh, mxs, sh, ss);
    prep_kernel<<<MM / 256, 256>>>(logits, src, av, mxh, mxs);
    sum_kernel<<<MM / 256, 256>>>(logits, av, src, mxh, mxs, sh, ss);
    scatter_kernel<<<EE, 128>>>(h, tgt, src, logits, av, mxh, mxs, sh, ss, out);
}

// round 16
// speedup vs baseline: 1.0545x; 1.0019x over previous
#include <cuda_runtime.h>
#include <cuda_bf16.h>
#include <math.h>
#include <stdint.h>

// Problem constants
#define BB 2
#define NN 10000
#define HH 128
#define EE 128000
#define MM (BB*EE)          // 256000 rows
#define GDIM 384            // 3*H

// ---------------- scratch (device globals; no runtime allocation) -------------
__device__ float g_giA[(size_t)MM*768];
__device__ float g_giB[(size_t)MM*768];
__device__ float g_gh[(size_t)MM*384];
__device__ float g_gh2[(size_t)MM*384];
__device__ float g_y0[(size_t)MM*256];
__device__ float g_y1[(size_t)MM*256];
__device__ float g_hh[(size_t)MM*256];
__device__ float g_hb1[(size_t)MM*128];
__device__ float g_logits[MM];
__device__ float g_av[MM];
__device__ unsigned g_mxh[NN*BB];
__device__ unsigned g_mxs[NN*BB];
__device__ float g_sh[NN*BB];
__device__ float g_ss[NN*BB];

// bf16 hi/lo activation buffers
__device__ __nv_bfloat16 g_x0h[(size_t)MM*128], g_x0l[(size_t)MM*128];
__device__ __nv_bfloat16 g_x1h[(size_t)MM*128], g_x1l[(size_t)MM*128];
__device__ __nv_bfloat16 g_y0h[(size_t)MM*256], g_y0l[(size_t)MM*256];
__device__ __nv_bfloat16 g_y1h[(size_t)MM*256], g_y1l[(size_t)MM*256];
__device__ __nv_bfloat16 g_hb1h[(size_t)MM*128], g_hb1l[(size_t)MM*128];

// packed pre-split weights: layout [cb][kc][r(128)][c(32)]
// regions: wih0f 0 | wih0b 49152 | whh0f 98304 | whh0b 147456 |
//          whh1b 196608 | wih1f 245760 (K=256) | wih1b 344064 (K=256)
#define WPK_TOTAL 442368
__device__ __nv_bfloat16 g_wpk_h[WPK_TOTAL];
__device__ __nv_bfloat16 g_wpk_l[WPK_TOTAL];

// ---------------- helpers -----------------------------------------------------
__device__ __forceinline__ unsigned enc_f(float x) {
    unsigned u = __float_as_uint(x);
    return (u & 0x80000000u) ? ~u : (u | 0x80000000u);
}
__device__ __forceinline__ float dec_f(unsigned v) {
    return (v & 0x80000000u) ? __uint_as_float(v ^ 0x80000000u) : __uint_as_float(~v);
}
#define ENC_NEG_INF 0x007FFFFFu

__device__ __forceinline__ float sigmoidf_(float x) { return 1.0f / (1.0f + expf(-x)); }

__device__ __forceinline__ uint32_t smem_u32(const void* p) {
    uint32_t a;
    asm("{ .reg .u64 t; cvta.to.shared.u64 t, %1; cvt.u32.u64 %0, t; }" : "=r"(a) : "l"(p));
    return a;
}

#define LDMX4(r0, r1, r2, r3, addr) \
    asm volatile("ldmatrix.sync.aligned.m8n8.x4.shared.b16 {%0,%1,%2,%3}, [%4];" \
                 : "=r"(r0), "=r"(r1), "=r"(r2), "=r"(r3) : "r"(addr))

#define MMA_BF16(c, a0, a1, a2, a3, b0, b1) \
    asm volatile("mma.sync.aligned.m16n8k16.row.col.f32.bf16.bf16.f32 " \
                 "{%0,%1,%2,%3}, {%4,%5,%6,%7}, {%8,%9}, {%0,%1,%2,%3};" \
                 : "+f"((c)[0]), "+f"((c)[1]), "+f"((c)[2]), "+f"((c)[3]) \
                 : "r"(a0), "r"(a1), "r"(a2), "r"(a3), "r"(b0), "r"(b1))

#define CPA16(dst, src) \
    asm volatile("cp.async.cg.shared.global [%0], [%1], 16;" :: "r"(dst), "l"(src))
#define CPA_COMMIT() asm volatile("cp.async.commit_group;" ::: "memory")
#define CPA_WAIT1() asm volatile("cp.async.wait_group 1;" ::: "memory")

__device__ __forceinline__ void split_bf16(float x, __nv_bfloat16& hi, __nv_bfloat16& lo) {
    hi = __float2bfloat16_rn(x);
    lo = __float2bfloat16_rn(x - __bfloat162float(hi));
}

// ---------------- weight pre-split/pack: ALL weights in one launch ---------------
__global__ void pack_all(const float* __restrict__ wih0f, const float* __restrict__ wih0b,
                         const float* __restrict__ whh0f, const float* __restrict__ whh0b,
                         const float* __restrict__ whh1b,
                         const float* __restrict__ wih1f, const float* __restrict__ wih1b,
                         __nv_bfloat16* __restrict__ outh,
                         __nv_bfloat16* __restrict__ outl) {
    int idx = blockIdx.x * blockDim.x + threadIdx.x;
    if (idx >= WPK_TOTAL) return;
    const float* W; int base, K;
    if      (idx < 49152)  { W = wih0f; base = 0;      K = 128; }
    else if (idx < 98304)  { W = wih0b; base = 49152;  K = 128; }
    else if (idx < 147456) { W = whh0f; base = 98304;  K = 128; }
    else if (idx < 196608) { W = whh0b; base = 147456; K = 128; }
    else if (idx < 245760) { W = whh1b; base = 196608; K = 128; }
    else if (idx < 344064) { W = wih1f; base = 245760; K = 256; }
    else                   { W = wih1b; base = 344064; K = 256; }
    int li = idx - base;
    int nkc = K >> 5;
    int c = li & 31;
    int r = (li >> 5) & 127;
    int kcb = li >> 12;
    int kc = kcb % nkc, cb = kcb / nkc;
    float v = W[(size_t)(cb * 128 + r) * K + kc * 32 + c];
    __nv_bfloat16 hi, lo; split_bf16(v, hi, lo);
    outh[idx] = hi; outl[idx] = lo;
}

// ---------------- gather (writes bf16 hi/lo) ------------------------------------
__global__ void gather_kernel(const float4* __restrict__ h,
                              const int* __restrict__ tgt,
                              const int* __restrict__ src,
                              __nv_bfloat16* __restrict__ x0h, __nv_bfloat16* __restrict__ x0l,
                              __nv_bfloat16* __restrict__ x1h, __nv_bfloat16* __restrict__ x1l) {
    long long idx = (long long)blockIdx.x * blockDim.x + threadIdx.x;
    int q = (int)(idx & 31);
    long long be = idx >> 5;
    int e = (int)(be % EE);
    int b = (int)(be / EE);
    int t = tgt[e], s = src[e];
    float4 vt = h[((long long)b * NN + t) * 32 + q];
    float4 vs = h[((long long)b * NN + s) * 32 + q];
    __nv_bfloat16 hh_[4], ll_[4];
    long long o = be * 128 + q * 4;
    split_bf16(vt.x, hh_[0], ll_[0]); split_bf16(vt.y, hh_[1], ll_[1]);
    split_bf16(vt.z, hh_[2], ll_[2]); split_bf16(vt.w, hh_[3], ll_[3]);
    *(ulonglong1*)(x0h + o) = *(ulonglong1*)hh_;
    *(ulonglong1*)(x0l + o) = *(ulonglong1*)ll_;
    split_bf16(vs.x, hh_[0], ll_[0]); split_bf16(vs.y, hh_[1], ll_[1]);
    split_bf16(vs.z, hh_[2], ll_[2]); split_bf16(vs.w, hh_[3], ll_[3]);
    *(ulonglong1*)(x1h + o) = *(ulonglong1*)hh_;
    *(ulonglong1*)(x1l + o) = *(ulonglong1*)ll_;
}

// ---------------- bf16x3 HMMA GEMM, dual-job, 2-stage cp.async, 2 CTAs/SM --------
// Jobs A/B dispatch: jobB if blockIdx.x >= cbSplit OR blockIdx.y >= ySplit.
#define SBF 40
#define TILE_B (128 * SBF * 2)
#define STAGE_B (4 * TILE_B)     // 40960
#define PSMEM (2 * STAGE_B)      // 81920

__global__ void __launch_bounds__(256, 2) sgemm_dual(
        const __nv_bfloat16* __restrict__ AhA, const __nv_bfloat16* __restrict__ AlA,
        int ldaA,
        const __nv_bfloat16* __restrict__ WhA, const __nv_bfloat16* __restrict__ WlA,
        float* __restrict__ CA, int ldcA,
        const __nv_bfloat16* __restrict__ AhB, const __nv_bfloat16* __restrict__ AlB,
        int ldaB,
        const __nv_bfloat16* __restrict__ WhB, const __nv_bfloat16* __restrict__ WlB,
        float* __restrict__ CB, int ldcB,
        int nkc, int cbSplit, int ySplit) {
    extern __shared__ __align__(16) char smem[];
    uint32_t sb = smem_u32(smem);

    int tid = threadIdx.x;
    int lane = tid & 31;
    int wid = tid >> 5;
    int warp_m = wid & 3;
    int warp_n = wid >> 2;

    int cb = blockIdx.x;
    int yb = blockIdx.y;
    bool jobB = (cb >= cbSplit) || (yb >= ySplit);
    if (cb >= cbSplit) cb -= cbSplit;
    if (yb >= ySplit)  yb -= ySplit;
    const __nv_bfloat16* Ah = jobB ? AhB : AhA;
    const __nv_bfloat16* Al = jobB ? AlB : AlA;
    const __nv_bfloat16* Wh = jobB ? WhB : WhA;
    const __nv_bfloat16* Wl = jobB ? WlB : WlA;
    float* C  = jobB ? CB : CA;
    int lda   = jobB ? ldaB : ldaA;
    int ldc   = jobB ? ldcB : ldcA;
    int rowBlk = yb * 128;

    float c[2][8][4];
    #pragma unroll
    for (int i = 0; i < 2; i++)
        #pragma unroll
        for (int j = 0; j < 8; j++)
            #pragma unroll
            for (int q = 0; q < 4; q++) c[i][j][q] = 0.0f;

    auto issue = [&](int kc, int s) {
        #pragma unroll
        for (int q = 0; q < 8; q++) {
            int id = tid + q * 256;
            int tile = id >> 9;
            int rem = id & 511;
            int r = rem >> 2, c16 = rem & 3;
            uint32_t dst = sb + s * STAGE_B + tile * TILE_B + r * (SBF * 2) + c16 * 16;
            const __nv_bfloat16* src;
            if (tile == 0)
                src = Ah + (size_t)(rowBlk + r) * lda + kc * 32 + c16 * 8;
            else if (tile == 1)
                src = Al + (size_t)(rowBlk + r) * lda + kc * 32 + c16 * 8;
            else if (tile == 2)
                src = Wh + ((size_t)(cb * nkc + kc) << 12) + r * 32 + c16 * 8;
            else
                src = Wl + ((size_t)(cb * nkc + kc) << 12) + r * 32 + c16 * 8;
            CPA16(dst, src);
        }
    };

    int a_r = lane & 15, a_c = (lane >> 4) << 3;
    int b_r = (lane & 7) + ((lane >> 4) << 3);
    int b_c = ((lane >> 3) & 1) << 3;

    issue(0, 0);
    CPA_COMMIT();

    for (int kc = 0; kc < nkc; kc++) {
        if (kc + 1 < nkc) issue(kc + 1, (kc + 1) & 1);
        CPA_COMMIT();
        CPA_WAIT1();
        __syncthreads();

        uint32_t st = sb + (kc & 1) * STAGE_B;
        uint32_t uAh = st, uAl = st + TILE_B, uWh = st + 2 * TILE_B, uWl = st + 3 * TILE_B;

        #pragma unroll
        for (int ks = 0; ks < 2; ks++) {
            uint32_t ah[2][4], al[2][4];
            #pragma unroll
            for (int mt = 0; mt < 2; mt++) {
                uint32_t eoff = (uint32_t)((warp_m * 32 + mt * 16 + a_r) * SBF
                                           + ks * 16 + a_c) * 2;
                LDMX4(ah[mt][0], ah[mt][1], ah[mt][2], ah[mt][3], uAh + eoff);
                LDMX4(al[mt][0], al[mt][1], al[mt][2], al[mt][3], uAl + eoff);
            }
            #pragma unroll
            for (int np = 0; np < 4; np++) {
                uint32_t bh[4], bl[4];
                uint32_t eoff = (uint32_t)((warp_n * 64 + np * 16 + b_r) * SBF
                                           + ks * 16 + b_c) * 2;
                LDMX4(bh[0], bh[1], bh[2], bh[3], uWh + eoff);
                LDMX4(bl[0], bl[1], bl[2], bl[3], uWl + eoff);
                #pragma unroll
                for (int mt = 0; mt < 2; mt++) {
                    float* c0 = c[mt][np * 2];
                    float* c1 = c[mt][np * 2 + 1];
                    MMA_BF16(c0, ah[mt][0], ah[mt][1], ah[mt][2], ah[mt][3], bh[0], bh[1]);
                    MMA_BF16(c0, ah[mt][0], ah[mt][1], ah[mt][2], ah[mt][3], bl[0], bl[1]);
                    MMA_BF16(c0, al[mt][0], al[mt][1], al[mt][2], al[mt][3], bh[0], bh[1]);
                    MMA_BF16(c1, ah[mt][0], ah[mt][1], ah[mt][2], ah[mt][3], bh[2], bh[3]);
                    MMA_BF16(c1, ah[mt][0], ah[mt][1], ah[mt][2], ah[mt][3], bl[2], bl[3]);
                    MMA_BF16(c1, al[mt][0], al[mt][1], al[mt][2], al[mt][3], bh[2], bh[3]);
                }
            }
        }
        __syncthreads();
    }

    int colBlk = cb * 128;
    #pragma unroll
    for (int mt = 0; mt < 2; mt++) {
        int r = rowBlk + warp_m * 32 + mt * 16 + (lane >> 2);
        #pragma unroll
        for (int nt = 0; nt < 8; nt++) {
            int col = colBlk + warp_n * 64 + nt * 8 + (lane & 3) * 2;
            *(float2*)(C + (size_t)r * ldc + col) =
                make_float2(c[mt][nt][0], c[mt][nt][1]);
            *(float2*)(C + (size_t)(r + 8) * ldc + col) =
                make_float2(c[mt][nt][2], c[mt][nt][3]);
        }
    }
}

// ---------------- GRU pointwise (nullable fp32 out; optional bf16 hi/lo) ---------
__global__ void gru_pointwise(const float* __restrict__ gi, int gi_stride,
                              const float* __restrict__ gh,
                              const float* __restrict__ hp, int hp_stride,
                              const float* __restrict__ b_ih,
                              const float* __restrict__ b_hh,
                              float* __restrict__ out, int out_stride,
                              __nv_bfloat16* __restrict__ outh,
                              __nv_bfloat16* __restrict__ outl, int bf_stride) {
    long long idx = (long long)blockIdx.x * blockDim.x + threadIdx.x;
    int j = (int)(idx & 127);
    long long m = idx >> 7;
    const float* gir = gi + m * (long long)gi_stride;
    float ir = gir[j]        + b_ih[j];
    float iz = gir[128 + j]  + b_ih[128 + j];
    float in_ = gir[256 + j] + b_ih[256 + j];
    float hr, hz, hn;
    if (gh) {
        const float* ghr = gh + m * GDIM;
        hr = ghr[j]       + b_hh[j];
        hz = ghr[128 + j] + b_hh[128 + j];
        hn = ghr[256 + j] + b_hh[256 + j];
    } else {
        hr = b_hh[j]; hz = b_hh[128 + j]; hn = b_hh[256 + j];
    }
    float r = sigmoidf_(ir + hr);
    float z = sigmoidf_(iz + hz);
    float n = tanhf(in_ + r * hn);
    float hv = hp ? hp[m * (long long)hp_stride + j] : 0.0f;
    float o = (1.0f - z) * n + z * hv;
    if (out) out[m * (long long)out_stride + j] = o;
    if (outh) {
        __nv_bfloat16 hi, lo; split_bf16(o, hi, lo);
        outh[m * (long long)bf_stride + j] = hi;
        outl[m * (long long)bf_stride + j] = lo;
    }
}

// ---------------- logits ---------------------------------------------------------
__global__ void logits_kernel(const float* __restrict__ hh,
                              const float* __restrict__ w_con,
                              const float* __restrict__ b_con,
                              float* __restrict__ logits) {
    long long gth = (long long)blockIdx.x * blockDim.x + threadIdx.x;
    long long warp = gth >> 5;
    int lane = (int)(gth & 31);
    const float* row = hh + warp * 256;
    float s = 0.0f;
    #pragma unroll
    for (int k = 0; k < 8; k++) s = fmaf(row[lane + k * 32], w_con[lane + k * 32], s);
    #pragma unroll
    for (int o = 16; o > 0; o >>= 1) s += __shfl_xor_sync(0xFFFFFFFFu, s, o);
    if (lane == 0) {
        float x = s + b_con[0];
        logits[warp] = 0.5f * x * (1.0f + erff(x * 0.70710678118654752440f));
    }
}

// ---------------- JAX threefry2x32 gumbel, partitionable mode -------------------
__device__ __forceinline__ void threefry2x32_dev(unsigned k0, unsigned k1,
                                                 unsigned& x0, unsigned& x1) {
    unsigned ks2 = k0 ^ k1 ^ 0x1BD11BDAu;
    x0 += k0; x1 += k1;
#define TFR(r) { x0 += x1; x1 = (x1 << (r)) | (x1 >> (32 - (r))); x1 ^= x0; }
#define TFG(a, b, c, d, A0, A1, INC) TFR(a) TFR(b) TFR(c) TFR(d) x0 += (A0); x1 += (A1) + (INC);
    TFG(13, 15, 26, 6,  k1,  ks2, 1u)
    TFG(17, 29, 16, 24, ks2, k0,  2u)
    TFG(13, 15, 26, 6,  k0,  k1,  3u)
    TFG(17, 29, 16, 24, k1,  ks2, 4u)
    TFG(13, 15, 26, 6,  ks2, k0,  5u)
#undef TFR
#undef TFG
}

__device__ __forceinline__ float bits_to_gumbel(unsigned bits) {
    float u = __uint_as_float((bits >> 9) | 0x3f800000u) - 1.0f;
    float v = fmaxf(u, 1.175494350822287508e-38f);
    return -logf(-logf(v));
}

// ---------------- init / segment softmax / scatter -------------------------------
__global__ void init_kernel(float* __restrict__ out,
                            unsigned* __restrict__ mxh, unsigned* __restrict__ mxs,
                            float* __restrict__ sh, float* __restrict__ ss) {
    int i = blockIdx.x * blockDim.x + threadIdx.x;
    if (i < BB * NN * HH) out[i] = 0.0f;
    if (i < NN * BB) { mxh[i] = ENC_NEG_INF; mxs[i] = ENC_NEG_INF; sh[i] = 0.0f; ss[i] = 0.0f; }
}

__global__ void prep_kernel(const float* __restrict__ logits,
                            const int* __restrict__ src,
                            float* __restrict__ av,
                            unsigned* __restrict__ mxh, unsigned* __restrict__ mxs) {
    int f = blockIdx.x * blockDim.x + threadIdx.x;   // f = e*B + b
    int e = f >> 1, b = f & 1;
    unsigned t0 = 0u, t1 = (unsigned)f;
    threefry2x32_dev(0u, 42u, t0, t1);
    float g = bits_to_gumbel(t0 ^ t1);
    float l = logits[(size_t)b * EE + e];
    float a = (l + g) / 0.1f;
    av[f] = a;
    int n2 = src[e] * BB + b;
    atomicMax(&mxh[n2], enc_f(a));
    atomicMax(&mxs[n2], enc_f(l));
}

__global__ void sum_kernel(const float* __restrict__ logits, const float* __restrict__ av,
                           const int* __restrict__ src,
                           const unsigned* __restrict__ mxh, const unsigned* __restrict__ mxs,
                           float* __restrict__ sh, float* __restrict__ ss) {
    int f = blockIdx.x * blockDim.x + threadIdx.x;
    int e = f >> 1, b = f & 1;
    int n2 = src[e] * BB + b;
    atomicAdd(&sh[n2], expf(av[f] - dec_f(mxh[n2])));
    atomicAdd(&ss[n2], expf(logits[(size_t)b * EE + e] - dec_f(mxs[n2])));
}

__global__ void scatter_kernel(const float* __restrict__ h,
                               const int* __restrict__ tgt, const int* __restrict__ src,
                               const float* __restrict__ logits, const float* __restrict__ av,
                               const unsigned* __restrict__ mxh, const unsigned* __restrict__ mxs,
                               const float* __restrict__ sh, const float* __restrict__ ss,
                               float* __restrict__ out) {
    int e = blockIdx.x;
    int j = threadIdx.x;
    int s = src[e], t = tgt[e];
    #pragma unroll
    for (int b = 0; b < BB; b++) {
        int n2 = s * BB + b;
        float a = av[e * BB + b];
        float l = logits[(size_t)b * EE + e];
        float w = (expf(a - dec_f(mxh[n2])) / sh[n2]) * (expf(l - dec_f(mxs[n2])) / ss[n2]);
        float hv = h[((size_t)b * NN + s) * HH + j];
        atomicAdd(&out[((size_t)b * NN + t) * HH + j], hv * w);
    }
}

// ---------------- host orchestration ---------------------------------------------
extern "C" void kernel_launch(void* const* d_in, const int* in_sizes, int n_in,
                              void* d_out, int out_size) {
    static const int map_ins[20]   = {0,1,2,3,4,5,6,7,8,9,10,11,12,13,14,15,16,17,18,19};
    static const int map_alpha[20] = {10,9,17,13,6,2,16,12,5,1,19,15,8,4,18,14,7,3,11,0};
    const int* mp = (in_sizes[0] == BB * NN * HH) ? map_ins : map_alpha;

    const float* h   = (const float*)d_in[mp[0]];
    const int* ei    = (const int*)d_in[mp[1]];
    const int* tgt   = ei;
    const int* src   = ei + EE;
    const float* wih0f = (const float*)d_in[mp[2]];
    const float* whh0f = (const float*)d_in[mp[3]];
    const float* bih0f = (const float*)d_in[mp[4]];
    const float* bhh0f = (const float*)d_in[mp[5]];
    const float* wih0b = (const float*)d_in[mp[6]];
    const float* whh0b = (const float*)d_in[mp[7]];
    const float* bih0b = (const float*)d_in[mp[8]];
    const float* bhh0b = (const float*)d_in[mp[9]];
    const float* wih1f = (const float*)d_in[mp[10]];
    const float* bih1f = (const float*)d_in[mp[12]];
    const float* bhh1f = (const float*)d_in[mp[13]];
    const float* wih1b = (const float*)d_in[mp[14]];
    const float* whh1b = (const float*)d_in[mp[15]];
    const float* bih1b = (const float*)d_in[mp[16]];
    const float* bhh1b = (const float*)d_in[mp[17]];
    const float* wcon  = (const float*)d_in[mp[18]];
    const float* bcon  = (const float*)d_in[mp[19]];
    float* out = (float*)d_out;

    float *giA, *giB, *gh, *gh2, *y0, *y1, *hhb, *hb1, *logits, *av, *sh, *ss;
    unsigned *mxh, *mxs;
    __nv_bfloat16 *x0h, *x0l, *x1h, *x1l, *y0h, *y0l, *y1h, *y1l, *hb1h, *hb1l;
    __nv_bfloat16 *wpkh, *wpkl;
    cudaGetSymbolAddress((void**)&giA, g_giA);
    cudaGetSymbolAddress((void**)&giB, g_giB);
    cudaGetSymbolAddress((void**)&gh, g_gh);
    cudaGetSymbolAddress((void**)&gh2, g_gh2);
    cudaGetSymbolAddress((void**)&y0, g_y0);
    cudaGetSymbolAddress((void**)&y1, g_y1);
    cudaGetSymbolAddress((void**)&hhb, g_hh);
    cudaGetSymbolAddress((void**)&hb1, g_hb1);
    cudaGetSymbolAddress((void**)&logits, g_logits);
    cudaGetSymbolAddress((void**)&av, g_av);
    cudaGetSymbolAddress((void**)&mxh, g_mxh);
    cudaGetSymbolAddress((void**)&mxs, g_mxs);
    cudaGetSymbolAddress((void**)&sh, g_sh);
    cudaGetSymbolAddress((void**)&ss, g_ss);
    cudaGetSymbolAddress((void**)&x0h, g_x0h);
    cudaGetSymbolAddress((void**)&x0l, g_x0l);
    cudaGetSymbolAddress((void**)&x1h, g_x1h);
    cudaGetSymbolAddress((void**)&x1l, g_x1l);
    cudaGetSymbolAddress((void**)&y0h, g_y0h);
    cudaGetSymbolAddress((void**)&y0l, g_y0l);
    cudaGetSymbolAddress((void**)&y1h, g_y1h);
    cudaGetSymbolAddress((void**)&y1l, g_y1l);
    cudaGetSymbolAddress((void**)&hb1h, g_hb1h);
    cudaGetSymbolAddress((void**)&hb1l, g_hb1l);
    cudaGetSymbolAddress((void**)&wpkh, g_wpk_h);
    cudaGetSymbolAddress((void**)&wpkl, g_wpk_l);

    cudaFuncSetAttribute(sgemm_dual, cudaFuncAttributeMaxDynamicSharedMemorySize, PSMEM);

    __nv_bfloat16 *pw0  = wpkh + 0,      *pw0_l  = wpkl + 0;        // [wih0f|wih0b]
    __nv_bfloat16 *ph0f = wpkh + 98304,  *ph0f_l = wpkl + 98304;    // whh0f
    __nv_bfloat16 *ph0b = wpkh + 147456, *ph0b_l = wpkl + 147456;   // whh0b
    __nv_bfloat16 *ph1b = wpkh + 196608, *ph1b_l = wpkl + 196608;   // whh1b
    __nv_bfloat16 *pw1  = wpkh + 245760, *pw1_l  = wpkl + 245760;   // [wih1f|wih1b]
    __nv_bfloat16 *pw1b = wpkh + 344064, *pw1b_l = wpkl + 344064;   // wih1b

    pack_all<<<(WPK_TOTAL + 255) / 256, 256>>>(wih0f, wih0b, whh0f, whh0b, whh1b,
                                               wih1f, wih1b, wpkh, wpkl);

    const int PW_BLOCKS = (MM * 128) / 256;

    gather_kernel<<<(MM * 32) / 256, 256>>>((const float4*)h, tgt, src,
                                            x0h, x0l, x1h, x1l);

    // ---- merged input GEMMs: giA = x0 @ [W0f|W0b], giB = x1 @ [W0f|W0b] ----
    sgemm_dual<<<dim3(6, 4000), 256, PSMEM>>>(
        x0h, x0l, 128, pw0, pw0_l, giA, 768,
        x1h, x1l, 128, pw0, pw0_l, giB, 768,
        4, 6, 2000);

    // f0 = cell_f(x0, 0)   b1 = cell_b(x1, 0)
    gru_pointwise<<<PW_BLOCKS, 256>>>(giA, 768, nullptr, nullptr, 0, bih0f, bhh0f,
                                      y0, 256, y0h, y0l, 256);
    gru_pointwise<<<PW_BLOCKS, 256>>>(giB + 384, 768, nullptr, nullptr, 0, bih0b, bhh0b,
                                      y1 + 128, 256, y1h + 128, y1l + 128, 256);

    // ---- merged recurrent GEMMs: gh = f0 @ Whh0f, gh2 = b1 @ Whh0b ----
    sgemm_dual<<<dim3(3, 4000), 256, PSMEM>>>(
        y0h, y0l, 256, ph0f, ph0f_l, gh, 384,
        y1h + 128, y1l + 128, 256, ph0b, ph0b_l, gh2, 384,
        4, 3, 2000);

    // f1 = cell_f(x1, f0)   b0 = cell_b(x0, b1)
    gru_pointwise<<<PW_BLOCKS, 256>>>(giB, 768, gh, y0, 256, bih0f, bhh0f,
                                      nullptr, 0, y1h, y1l, 256);
    gru_pointwise<<<PW_BLOCKS, 256>>>(giA + 384, 768, gh2, y1 + 128, 256, bih0b, bhh0b,
                                      nullptr, 0, y0h + 128, y0l + 128, 256);

    // ---- merged layer-1 GEMMs: giA = y0 @ [W1f|W1b] (6cb), giB = y1 @ W1b (3cb) ----
    sgemm_dual<<<dim3(9, 2000), 256, PSMEM>>>(
        y0h, y0l, 256, pw1, pw1_l, giA, 768,
        y1h, y1l, 256, pw1b, pw1b_l, giB, 384,
        8, 6, 2000);

    // f0' = cell_f1(y0, 0)   b1' = cell_b1(y1, 0)
    gru_pointwise<<<PW_BLOCKS, 256>>>(giA, 768, nullptr, nullptr, 0, bih1f, bhh1f,
                                      hhb, 256, nullptr, nullptr, 0);
    gru_pointwise<<<PW_BLOCKS, 256>>>(giB, 384, nullptr, nullptr, 0, bih1b, bhh1b,
                                      hb1, 128, hb1h, hb1l, 128);

    // b0' = cell_b1(y0, b1')
    sgemm_dual<<<dim3(3, 2000), 256, PSMEM>>>(
        hb1h, hb1l, 128, ph1b, ph1b_l, gh, 384,
        hb1h, hb1l, 128, ph1b, ph1b_l, gh, 384,
        4, 1000, 100000);
    gru_pointwise<<<PW_BLOCKS, 256>>>(giA + 384, 768, gh, hb1, 128, bih1b, bhh1b,
                                      hhb + 128, 256, nullptr, nullptr, 0);

    // ---- logits, segment softmaxes (gumbel fused into prep), weighted scatter ----
    logits_kernel<<<(MM * 32) / 256, 256>>>(hhb, wcon, bcon, logits);
    init_kernel<<<(BB * NN * HH + 255) / 256, 256>>>(out, mxh, mxs, sh, ss);
    prep_kernel<<<MM / 256, 256>>>(logits, src, av, mxh, mxs);
    sum_kernel<<<MM / 256, 256>>>(logits, av, src, mxh, mxs, sh, ss);
    scatter_kernel<<<EE, 128>>>(h, tgt, src, logits, av, mxh, mxs, sh, ss, out);
}

// round 17
// speedup vs baseline: 1.1366x; 1.0778x over previous
#include <cuda_runtime.h>
#include <cuda_bf16.h>
#include <math.h>
#include <stdint.h>

// Problem constants
#define BB 2
#define NN 10000
#define HH 128
#define EE 128000
#define MM (BB*EE)          // 256000 rows
#define GDIM 384            // 3*H

// ---------------- scratch (device globals; no runtime allocation) -------------
__device__ float g_giA[(size_t)MM*768];
__device__ float g_giB[(size_t)MM*768];
__device__ float g_gh[(size_t)MM*384];
__device__ float g_gh2[(size_t)MM*384];
__device__ float g_y0[(size_t)MM*256];
__device__ float g_y1[(size_t)MM*256];
__device__ float g_hh[(size_t)MM*256];
__device__ float g_hb1[(size_t)MM*128];
__device__ float g_logits[MM];
__device__ float g_av[MM];
__device__ unsigned g_mxh[NN*BB];
__device__ unsigned g_mxs[NN*BB];
__device__ float g_sh[NN*BB];
__device__ float g_ss[NN*BB];

// bf16 hi/lo activation buffers
__device__ __nv_bfloat16 g_x0h[(size_t)MM*128], g_x0l[(size_t)MM*128];
__device__ __nv_bfloat16 g_x1h[(size_t)MM*128], g_x1l[(size_t)MM*128];
__device__ __nv_bfloat16 g_y0h[(size_t)MM*256], g_y0l[(size_t)MM*256];
__device__ __nv_bfloat16 g_y1h[(size_t)MM*256], g_y1l[(size_t)MM*256];
__device__ __nv_bfloat16 g_hb1h[(size_t)MM*128], g_hb1l[(size_t)MM*128];

// packed pre-split weights: layout [cb][kc][r(128)][c(32)]
#define WPK_TOTAL 442368
__device__ __nv_bfloat16 g_wpk_h[WPK_TOTAL];
__device__ __nv_bfloat16 g_wpk_l[WPK_TOTAL];

// ---------------- helpers -----------------------------------------------------
__device__ __forceinline__ unsigned enc_f(float x) {
    unsigned u = __float_as_uint(x);
    return (u & 0x80000000u) ? ~u : (u | 0x80000000u);
}
__device__ __forceinline__ float dec_f(unsigned v) {
    return (v & 0x80000000u) ? __uint_as_float(v ^ 0x80000000u) : __uint_as_float(~v);
}
#define ENC_NEG_INF 0x007FFFFFu

__device__ __forceinline__ float sigmoidf_(float x) { return 1.0f / (1.0f + expf(-x)); }

__device__ __forceinline__ uint32_t smem_u32(const void* p) {
    uint32_t a;
    asm("{ .reg .u64 t; cvta.to.shared.u64 t, %1; cvt.u32.u64 %0, t; }" : "=r"(a) : "l"(p));
    return a;
}

#define LDMX4(r0, r1, r2, r3, addr) \
    asm volatile("ldmatrix.sync.aligned.m8n8.x4.shared.b16 {%0,%1,%2,%3}, [%4];" \
                 : "=r"(r0), "=r"(r1), "=r"(r2), "=r"(r3) : "r"(addr))

#define MMA_BF16(c, a0, a1, a2, a3, b0, b1) \
    asm volatile("mma.sync.aligned.m16n8k16.row.col.f32.bf16.bf16.f32 " \
                 "{%0,%1,%2,%3}, {%4,%5,%6,%7}, {%8,%9}, {%0,%1,%2,%3};" \
                 : "+f"((c)[0]), "+f"((c)[1]), "+f"((c)[2]), "+f"((c)[3]) \
                 : "r"(a0), "r"(a1), "r"(a2), "r"(a3), "r"(b0), "r"(b1))

#define CPA16(dst, src) \
    asm volatile("cp.async.cg.shared.global [%0], [%1], 16;" :: "r"(dst), "l"(src))
#define CPA_COMMIT() asm volatile("cp.async.commit_group;" ::: "memory")
#define CPA_WAIT1() asm volatile("cp.async.wait_group 1;" ::: "memory")

__device__ __forceinline__ void split_bf16(float x, __nv_bfloat16& hi, __nv_bfloat16& lo) {
    hi = __float2bfloat16_rn(x);
    lo = __float2bfloat16_rn(x - __bfloat162float(hi));
}

// ---------------- weight pre-split/pack: ALL weights in one launch ---------------
__global__ void pack_all(const float* __restrict__ wih0f, const float* __restrict__ wih0b,
                         const float* __restrict__ whh0f, const float* __restrict__ whh0b,
                         const float* __restrict__ whh1b,
                         const float* __restrict__ wih1f, const float* __restrict__ wih1b,
                         __nv_bfloat16* __restrict__ outh,
                         __nv_bfloat16* __restrict__ outl) {
    int idx = blockIdx.x * blockDim.x + threadIdx.x;
    if (idx >= WPK_TOTAL) return;
    const float* W; int base, K;
    if      (idx < 49152)  { W = wih0f; base = 0;      K = 128; }
    else if (idx < 98304)  { W = wih0b; base = 49152;  K = 128; }
    else if (idx < 147456) { W = whh0f; base = 98304;  K = 128; }
    else if (idx < 196608) { W = whh0b; base = 147456; K = 128; }
    else if (idx < 245760) { W = whh1b; base = 196608; K = 128; }
    else if (idx < 344064) { W = wih1f; base = 245760; K = 256; }
    else                   { W = wih1b; base = 344064; K = 256; }
    int li = idx - base;
    int nkc = K >> 5;
    int c = li & 31;
    int r = (li >> 5) & 127;
    int kcb = li >> 12;
    int kc = kcb % nkc, cb = kcb / nkc;
    float v = W[(size_t)(cb * 128 + r) * K + kc * 32 + c];
    __nv_bfloat16 hi, lo; split_bf16(v, hi, lo);
    outh[idx] = hi; outl[idx] = lo;
}

// ---------------- gather (writes bf16 hi/lo) ------------------------------------
__global__ void gather_kernel(const float4* __restrict__ h,
                              const int* __restrict__ tgt,
                              const int* __restrict__ src,
                              __nv_bfloat16* __restrict__ x0h, __nv_bfloat16* __restrict__ x0l,
                              __nv_bfloat16* __restrict__ x1h, __nv_bfloat16* __restrict__ x1l) {
    long long idx = (long long)blockIdx.x * blockDim.x + threadIdx.x;
    int q = (int)(idx & 31);
    long long be = idx >> 5;
    int e = (int)(be % EE);
    int b = (int)(be / EE);
    int t = tgt[e], s = src[e];
    float4 vt = h[((long long)b * NN + t) * 32 + q];
    float4 vs = h[((long long)b * NN + s) * 32 + q];
    __nv_bfloat16 hh_[4], ll_[4];
    long long o = be * 128 + q * 4;
    split_bf16(vt.x, hh_[0], ll_[0]); split_bf16(vt.y, hh_[1], ll_[1]);
    split_bf16(vt.z, hh_[2], ll_[2]); split_bf16(vt.w, hh_[3], ll_[3]);
    *(ulonglong1*)(x0h + o) = *(ulonglong1*)hh_;
    *(ulonglong1*)(x0l + o) = *(ulonglong1*)ll_;
    split_bf16(vs.x, hh_[0], ll_[0]); split_bf16(vs.y, hh_[1], ll_[1]);
    split_bf16(vs.z, hh_[2], ll_[2]); split_bf16(vs.w, hh_[3], ll_[3]);
    *(ulonglong1*)(x1h + o) = *(ulonglong1*)hh_;
    *(ulonglong1*)(x1l + o) = *(ulonglong1*)ll_;
}

// ---------------- bf16x3 HMMA GEMM, dual-job, 2-stage cp.async, 2 CTAs/SM --------
#define SBF 40
#define TILE_B (128 * SBF * 2)
#define STAGE_B (4 * TILE_B)     // 40960
#define PSMEM (2 * STAGE_B)      // 81920

__global__ void __launch_bounds__(256, 2) sgemm_dual(
        const __nv_bfloat16* __restrict__ AhA, const __nv_bfloat16* __restrict__ AlA,
        int ldaA,
        const __nv_bfloat16* __restrict__ WhA, const __nv_bfloat16* __restrict__ WlA,
        float* __restrict__ CA, int ldcA,
        const __nv_bfloat16* __restrict__ AhB, const __nv_bfloat16* __restrict__ AlB,
        int ldaB,
        const __nv_bfloat16* __restrict__ WhB, const __nv_bfloat16* __restrict__ WlB,
        float* __restrict__ CB, int ldcB,
        int nkc, int cbSplit, int ySplit) {
    extern __shared__ __align__(16) char smem[];
    uint32_t sb = smem_u32(smem);

    int tid = threadIdx.x;
    int lane = tid & 31;
    int wid = tid >> 5;
    int warp_m = wid & 3;
    int warp_n = wid >> 2;

    int cb = blockIdx.x;
    int yb = blockIdx.y;
    bool jobB = (cb >= cbSplit) || (yb >= ySplit);
    if (cb >= cbSplit) cb -= cbSplit;
    if (yb >= ySplit)  yb -= ySplit;
    const __nv_bfloat16* Ah = jobB ? AhB : AhA;
    const __nv_bfloat16* Al = jobB ? AlB : AlA;
    const __nv_bfloat16* Wh = jobB ? WhB : WhA;
    const __nv_bfloat16* Wl = jobB ? WlB : WlA;
    float* C  = jobB ? CB : CA;
    int lda   = jobB ? ldaB : ldaA;
    int ldc   = jobB ? ldcB : ldcA;
    int rowBlk = yb * 128;

    float c[2][8][4];
    #pragma unroll
    for (int i = 0; i < 2; i++)
        #pragma unroll
        for (int j = 0; j < 8; j++)
            #pragma unroll
            for (int q = 0; q < 4; q++) c[i][j][q] = 0.0f;

    auto issue = [&](int kc, int s) {
        #pragma unroll
        for (int q = 0; q < 8; q++) {
            int id = tid + q * 256;
            int tile = id >> 9;
            int rem = id & 511;
            int r = rem >> 2, c16 = rem & 3;
            uint32_t dst = sb + s * STAGE_B + tile * TILE_B + r * (SBF * 2) + c16 * 16;
            const __nv_bfloat16* src;
            if (tile == 0)
                src = Ah + (size_t)(rowBlk + r) * lda + kc * 32 + c16 * 8;
            else if (tile == 1)
                src = Al + (size_t)(rowBlk + r) * lda + kc * 32 + c16 * 8;
            else if (tile == 2)
                src = Wh + ((size_t)(cb * nkc + kc) << 12) + r * 32 + c16 * 8;
            else
                src = Wl + ((size_t)(cb * nkc + kc) << 12) + r * 32 + c16 * 8;
            CPA16(dst, src);
        }
    };

    int a_r = lane & 15, a_c = (lane >> 4) << 3;
    int b_r = (lane & 7) + ((lane >> 4) << 3);
    int b_c = ((lane >> 3) & 1) << 3;

    issue(0, 0);
    CPA_COMMIT();

    for (int kc = 0; kc < nkc; kc++) {
        if (kc + 1 < nkc) issue(kc + 1, (kc + 1) & 1);
        CPA_COMMIT();
        CPA_WAIT1();
        __syncthreads();

        uint32_t st = sb + (kc & 1) * STAGE_B;
        uint32_t uAh = st, uAl = st + TILE_B, uWh = st + 2 * TILE_B, uWl = st + 3 * TILE_B;

        #pragma unroll
        for (int ks = 0; ks < 2; ks++) {
            uint32_t ah[2][4], al[2][4];
            #pragma unroll
            for (int mt = 0; mt < 2; mt++) {
                uint32_t eoff = (uint32_t)((warp_m * 32 + mt * 16 + a_r) * SBF
                                           + ks * 16 + a_c) * 2;
                LDMX4(ah[mt][0], ah[mt][1], ah[mt][2], ah[mt][3], uAh + eoff);
                LDMX4(al[mt][0], al[mt][1], al[mt][2], al[mt][3], uAl + eoff);
            }
            #pragma unroll
            for (int np = 0; np < 4; np++) {
                uint32_t bh[4], bl[4];
                uint32_t eoff = (uint32_t)((warp_n * 64 + np * 16 + b_r) * SBF
                                           + ks * 16 + b_c) * 2;
                LDMX4(bh[0], bh[1], bh[2], bh[3], uWh + eoff);
                LDMX4(bl[0], bl[1], bl[2], bl[3], uWl + eoff);
                #pragma unroll
                for (int mt = 0; mt < 2; mt++) {
                    float* c0 = c[mt][np * 2];
                    float* c1 = c[mt][np * 2 + 1];
                    MMA_BF16(c0, ah[mt][0], ah[mt][1], ah[mt][2], ah[mt][3], bh[0], bh[1]);
                    MMA_BF16(c0, ah[mt][0], ah[mt][1], ah[mt][2], ah[mt][3], bl[0], bl[1]);
                    MMA_BF16(c0, al[mt][0], al[mt][1], al[mt][2], al[mt][3], bh[0], bh[1]);
                    MMA_BF16(c1, ah[mt][0], ah[mt][1], ah[mt][2], ah[mt][3], bh[2], bh[3]);
                    MMA_BF16(c1, ah[mt][0], ah[mt][1], ah[mt][2], ah[mt][3], bl[2], bl[3]);
                    MMA_BF16(c1, al[mt][0], al[mt][1], al[mt][2], al[mt][3], bh[2], bh[3]);
                }
            }
        }
        __syncthreads();
    }

    int colBlk = cb * 128;
    #pragma unroll
    for (int mt = 0; mt < 2; mt++) {
        int r = rowBlk + warp_m * 32 + mt * 16 + (lane >> 2);
        #pragma unroll
        for (int nt = 0; nt < 8; nt++) {
            int col = colBlk + warp_n * 64 + nt * 8 + (lane & 3) * 2;
            *(float2*)(C + (size_t)r * ldc + col) =
                make_float2(c[mt][nt][0], c[mt][nt][1]);
            *(float2*)(C + (size_t)(r + 8) * ldc + col) =
                make_float2(c[mt][nt][2], c[mt][nt][3]);
        }
    }
}

// ---------------- GRU pointwise, x4 vectorized -----------------------------------
// One thread handles 4 consecutive hidden units. grid = M*32/256 blocks.
__global__ void gru_pointwise(const float* __restrict__ gi, int gi_stride,
                              const float* __restrict__ gh,
                              const float* __restrict__ hp, int hp_stride,
                              const float* __restrict__ b_ih,
                              const float* __restrict__ b_hh,
                              float* __restrict__ out, int out_stride,
                              __nv_bfloat16* __restrict__ outh,
                              __nv_bfloat16* __restrict__ outl, int bf_stride) {
    long long idx = (long long)blockIdx.x * blockDim.x + threadIdx.x;  // M*32
    int jv = (int)(idx & 31) * 4;
    long long m = idx >> 5;
    const float* gir = gi + m * (long long)gi_stride;
    float4 ir4 = *(const float4*)(gir + jv);
    float4 iz4 = *(const float4*)(gir + 128 + jv);
    float4 in4 = *(const float4*)(gir + 256 + jv);
    float4 bi_r = *(const float4*)(b_ih + jv);
    float4 bi_z = *(const float4*)(b_ih + 128 + jv);
    float4 bi_n = *(const float4*)(b_ih + 256 + jv);
    float4 bh_r = *(const float4*)(b_hh + jv);
    float4 bh_z = *(const float4*)(b_hh + 128 + jv);
    float4 bh_n = *(const float4*)(b_hh + 256 + jv);

    float hr[4], hz[4], hn[4];
    if (gh) {
        const float* ghr = gh + m * GDIM;
        float4 a = *(const float4*)(ghr + jv);
        float4 b = *(const float4*)(ghr + 128 + jv);
        float4 c = *(const float4*)(ghr + 256 + jv);
        hr[0]=a.x+bh_r.x; hr[1]=a.y+bh_r.y; hr[2]=a.z+bh_r.z; hr[3]=a.w+bh_r.w;
        hz[0]=b.x+bh_z.x; hz[1]=b.y+bh_z.y; hz[2]=b.z+bh_z.z; hz[3]=b.w+bh_z.w;
        hn[0]=c.x+bh_n.x; hn[1]=c.y+bh_n.y; hn[2]=c.z+bh_n.z; hn[3]=c.w+bh_n.w;
    } else {
        hr[0]=bh_r.x; hr[1]=bh_r.y; hr[2]=bh_r.z; hr[3]=bh_r.w;
        hz[0]=bh_z.x; hz[1]=bh_z.y; hz[2]=bh_z.z; hz[3]=bh_z.w;
        hn[0]=bh_n.x; hn[1]=bh_n.y; hn[2]=bh_n.z; hn[3]=bh_n.w;
    }
    float hv[4] = {0.f, 0.f, 0.f, 0.f};
    if (hp) {
        float4 v = *(const float4*)(hp + m * (long long)hp_stride + jv);
        hv[0]=v.x; hv[1]=v.y; hv[2]=v.z; hv[3]=v.w;
    }
    float ir[4] = {ir4.x+bi_r.x, ir4.y+bi_r.y, ir4.z+bi_r.z, ir4.w+bi_r.w};
    float iz[4] = {iz4.x+bi_z.x, iz4.y+bi_z.y, iz4.z+bi_z.z, iz4.w+bi_z.w};
    float in_[4]= {in4.x+bi_n.x, in4.y+bi_n.y, in4.z+bi_n.z, in4.w+bi_n.w};

    float o[4];
    #pragma unroll
    for (int k = 0; k < 4; k++) {
        float r = sigmoidf_(ir[k] + hr[k]);
        float z = sigmoidf_(iz[k] + hz[k]);
        float n = tanhf(in_[k] + r * hn[k]);
        o[k] = (1.0f - z) * n + z * hv[k];
    }
    if (out)
        *(float4*)(out + m * (long long)out_stride + jv) =
            make_float4(o[0], o[1], o[2], o[3]);
    if (outh) {
        __nv_bfloat16 hb[4], lb[4];
        #pragma unroll
        for (int k = 0; k < 4; k++) split_bf16(o[k], hb[k], lb[k]);
        *(ulonglong1*)(outh + m * (long long)bf_stride + jv) = *(ulonglong1*)hb;
        *(ulonglong1*)(outl + m * (long long)bf_stride + jv) = *(ulonglong1*)lb;
    }
}

// ---------------- logits ---------------------------------------------------------
__global__ void logits_kernel(const float* __restrict__ hh,
                              const float* __restrict__ w_con,
                              const float* __restrict__ b_con,
                              float* __restrict__ logits) {
    long long gth = (long long)blockIdx.x * blockDim.x + threadIdx.x;
    long long warp = gth >> 5;
    int lane = (int)(gth & 31);
    const float* row = hh + warp * 256;
    float s = 0.0f;
    #pragma unroll
    for (int k = 0; k < 8; k++) s = fmaf(row[lane + k * 32], w_con[lane + k * 32], s);
    #pragma unroll
    for (int o = 16; o > 0; o >>= 1) s += __shfl_xor_sync(0xFFFFFFFFu, s, o);
    if (lane == 0) {
        float x = s + b_con[0];
        logits[warp] = 0.5f * x * (1.0f + erff(x * 0.70710678118654752440f));
    }
}

// ---------------- JAX threefry2x32 gumbel, partitionable mode -------------------
__device__ __forceinline__ void threefry2x32_dev(unsigned k0, unsigned k1,
                                                 unsigned& x0, unsigned& x1) {
    unsigned ks2 = k0 ^ k1 ^ 0x1BD11BDAu;
    x0 += k0; x1 += k1;
#define TFR(r) { x0 += x1; x1 = (x1 << (r)) | (x1 >> (32 - (r))); x1 ^= x0; }
#define TFG(a, b, c, d, A0, A1, INC) TFR(a) TFR(b) TFR(c) TFR(d) x0 += (A0); x1 += (A1) + (INC);
    TFG(13, 15, 26, 6,  k1,  ks2, 1u)
    TFG(17, 29, 16, 24, ks2, k0,  2u)
    TFG(13, 15, 26, 6,  k0,  k1,  3u)
    TFG(17, 29, 16, 24, k1,  ks2, 4u)
    TFG(13, 15, 26, 6,  ks2, k0,  5u)
#undef TFR
#undef TFG
}

__device__ __forceinline__ float bits_to_gumbel(unsigned bits) {
    float u = __uint_as_float((bits >> 9) | 0x3f800000u) - 1.0f;
    float v = fmaxf(u, 1.175494350822287508e-38f);
    return -logf(-logf(v));
}

// ---------------- init / segment softmax / scatter -------------------------------
__global__ void init_kernel(float* __restrict__ out,
                            unsigned* __restrict__ mxh, unsigned* __restrict__ mxs,
                            float* __restrict__ sh, float* __restrict__ ss) {
    int i = blockIdx.x * blockDim.x + threadIdx.x;
    if (i < BB * NN * HH) out[i] = 0.0f;
    if (i < NN * BB) { mxh[i] = ENC_NEG_INF; mxs[i] = ENC_NEG_INF; sh[i] = 0.0f; ss[i] = 0.0f; }
}

__global__ void prep_kernel(const float* __restrict__ logits,
                            const int* __restrict__ src,
                            float* __restrict__ av,
                            unsigned* __restrict__ mxh, unsigned* __restrict__ mxs) {
    int f = blockIdx.x * blockDim.x + threadIdx.x;   // f = e*B + b
    int e = f >> 1, b = f & 1;
    unsigned t0 = 0u, t1 = (unsigned)f;
    threefry2x32_dev(0u, 42u, t0, t1);
    float g = bits_to_gumbel(t0 ^ t1);
    float l = logits[(size_t)b * EE + e];
    float a = (l + g) / 0.1f;
    av[f] = a;
    int n2 = src[e] * BB + b;
    atomicMax(&mxh[n2], enc_f(a));
    atomicMax(&mxs[n2], enc_f(l));
}

__global__ void sum_kernel(const float* __restrict__ logits, const float* __restrict__ av,
                           const int* __restrict__ src,
                           const unsigned* __restrict__ mxh, const unsigned* __restrict__ mxs,
                           float* __restrict__ sh, float* __restrict__ ss) {
    int f = blockIdx.x * blockDim.x + threadIdx.x;
    int e = f >> 1, b = f & 1;
    int n2 = src[e] * BB + b;
    atomicAdd(&sh[n2], expf(av[f] - dec_f(mxh[n2])));
    atomicAdd(&ss[n2], expf(logits[(size_t)b * EE + e] - dec_f(mxs[n2])));
}

__global__ void scatter_kernel(const float* __restrict__ h,
                               const int* __restrict__ tgt, const int* __restrict__ src,
                               const float* __restrict__ logits, const float* __restrict__ av,
                               const unsigned* __restrict__ mxh, const unsigned* __restrict__ mxs,
                               const float* __restrict__ sh, const float* __restrict__ ss,
                               float* __restrict__ out) {
    int e = blockIdx.x;
    int j = threadIdx.x;
    int s = src[e], t = tgt[e];
    #pragma unroll
    for (int b = 0; b < BB; b++) {
        int n2 = s * BB + b;
        float a = av[e * BB + b];
        float l = logits[(size_t)b * EE + e];
        float w = (expf(a - dec_f(mxh[n2])) / sh[n2]) * (expf(l - dec_f(mxs[n2])) / ss[n2]);
        float hv = h[((size_t)b * NN + s) * HH + j];
        atomicAdd(&out[((size_t)b * NN + t) * HH + j], hv * w);
    }
}

// ---------------- host orchestration ---------------------------------------------
extern "C" void kernel_launch(void* const* d_in, const int* in_sizes, int n_in,
                              void* d_out, int out_size) {
    static const int map_ins[20]   = {0,1,2,3,4,5,6,7,8,9,10,11,12,13,14,15,16,17,18,19};
    static const int map_alpha[20] = {10,9,17,13,6,2,16,12,5,1,19,15,8,4,18,14,7,3,11,0};
    const int* mp = (in_sizes[0] == BB * NN * HH) ? map_ins : map_alpha;

    const float* h   = (const float*)d_in[mp[0]];
    const int* ei    = (const int*)d_in[mp[1]];
    const int* tgt   = ei;
    const int* src   = ei + EE;
    const float* wih0f = (const float*)d_in[mp[2]];
    const float* whh0f = (const float*)d_in[mp[3]];
    const float* bih0f = (const float*)d_in[mp[4]];
    const float* bhh0f = (const float*)d_in[mp[5]];
    const float* wih0b = (const float*)d_in[mp[6]];
    const float* whh0b = (const float*)d_in[mp[7]];
    const float* bih0b = (const float*)d_in[mp[8]];
    const float* bhh0b = (const float*)d_in[mp[9]];
    const float* wih1f = (const float*)d_in[mp[10]];
    const float* bih1f = (const float*)d_in[mp[12]];
    const float* bhh1f = (const float*)d_in[mp[13]];
    const float* wih1b = (const float*)d_in[mp[14]];
    const float* whh1b = (const float*)d_in[mp[15]];
    const float* bih1b = (const float*)d_in[mp[16]];
    const float* bhh1b = (const float*)d_in[mp[17]];
    const float* wcon  = (const float*)d_in[mp[18]];
    const float* bcon  = (const float*)d_in[mp[19]];
    float* out = (float*)d_out;

    float *giA, *giB, *gh, *gh2, *y0, *y1, *hhb, *hb1, *logits, *av, *sh, *ss;
    unsigned *mxh, *mxs;
    __nv_bfloat16 *x0h, *x0l, *x1h, *x1l, *y0h, *y0l, *y1h, *y1l, *hb1h, *hb1l;
    __nv_bfloat16 *wpkh, *wpkl;
    cudaGetSymbolAddress((void**)&giA, g_giA);
    cudaGetSymbolAddress((void**)&giB, g_giB);
    cudaGetSymbolAddress((void**)&gh, g_gh);
    cudaGetSymbolAddress((void**)&gh2, g_gh2);
    cudaGetSymbolAddress((void**)&y0, g_y0);
    cudaGetSymbolAddress((void**)&y1, g_y1);
    cudaGetSymbolAddress((void**)&hhb, g_hh);
    cudaGetSymbolAddress((void**)&hb1, g_hb1);
    cudaGetSymbolAddress((void**)&logits, g_logits);
    cudaGetSymbolAddress((void**)&av, g_av);
    cudaGetSymbolAddress((void**)&mxh, g_mxh);
    cudaGetSymbolAddress((void**)&mxs, g_mxs);
    cudaGetSymbolAddress((void**)&sh, g_sh);
    cudaGetSymbolAddress((void**)&ss, g_ss);
    cudaGetSymbolAddress((void**)&x0h, g_x0h);
    cudaGetSymbolAddress((void**)&x0l, g_x0l);
    cudaGetSymbolAddress((void**)&x1h, g_x1h);
    cudaGetSymbolAddress((void**)&x1l, g_x1l);
    cudaGetSymbolAddress((void**)&y0h, g_y0h);
    cudaGetSymbolAddress((void**)&y0l, g_y0l);
    cudaGetSymbolAddress((void**)&y1h, g_y1h);
    cudaGetSymbolAddress((void**)&y1l, g_y1l);
    cudaGetSymbolAddress((void**)&hb1h, g_hb1h);
    cudaGetSymbolAddress((void**)&hb1l, g_hb1l);
    cudaGetSymbolAddress((void**)&wpkh, g_wpk_h);
    cudaGetSymbolAddress((void**)&wpkl, g_wpk_l);

    cudaFuncSetAttribute(sgemm_dual, cudaFuncAttributeMaxDynamicSharedMemorySize, PSMEM);

    __nv_bfloat16 *pw0  = wpkh + 0,      *pw0_l  = wpkl + 0;        // [wih0f|wih0b]
    __nv_bfloat16 *ph0f = wpkh + 98304,  *ph0f_l = wpkl + 98304;    // whh0f
    __nv_bfloat16 *ph0b = wpkh + 147456, *ph0b_l = wpkl + 147456;   // whh0b
    __nv_bfloat16 *ph1b = wpkh + 196608, *ph1b_l = wpkl + 196608;   // whh1b
    __nv_bfloat16 *pw1  = wpkh + 245760, *pw1_l  = wpkl + 245760;   // [wih1f|wih1b]
    __nv_bfloat16 *pw1b = wpkh + 344064, *pw1b_l = wpkl + 344064;   // wih1b

    pack_all<<<(WPK_TOTAL + 255) / 256, 256>>>(wih0f, wih0b, whh0f, whh0b, whh1b,
                                               wih1f, wih1b, wpkh, wpkl);

    const int PWV_BLOCKS = (MM * 32) / 256;   // 32000 (x4 vectorized pointwise)

    gather_kernel<<<(MM * 32) / 256, 256>>>((const float4*)h, tgt, src,
                                            x0h, x0l, x1h, x1l);

    // ---- merged input GEMMs: giA = x0 @ [W0f|W0b], giB = x1 @ [W0f|W0b] ----
    sgemm_dual<<<dim3(6, 4000), 256, PSMEM>>>(
        x0h, x0l, 128, pw0, pw0_l, giA, 768,
        x1h, x1l, 128, pw0, pw0_l, giB, 768,
        4, 6, 2000);

    // f0 = cell_f(x0, 0)   b1 = cell_b(x1, 0)
    gru_pointwise<<<PWV_BLOCKS, 256>>>(giA, 768, nullptr, nullptr, 0, bih0f, bhh0f,
                                       y0, 256, y0h, y0l, 256);
    gru_pointwise<<<PWV_BLOCKS, 256>>>(giB + 384, 768, nullptr, nullptr, 0, bih0b, bhh0b,
                                       y1 + 128, 256, y1h + 128, y1l + 128, 256);

    // ---- merged recurrent GEMMs: gh = f0 @ Whh0f, gh2 = b1 @ Whh0b ----
    sgemm_dual<<<dim3(3, 4000), 256, PSMEM>>>(
        y0h, y0l, 256, ph0f, ph0f_l, gh, 384,
        y1h + 128, y1l + 128, 256, ph0b, ph0b_l, gh2, 384,
        4, 3, 2000);

    // f1 = cell_f(x1, f0)   b0 = cell_b(x0, b1)
    gru_pointwise<<<PWV_BLOCKS, 256>>>(giB, 768, gh, y0, 256, bih0f, bhh0f,
                                       nullptr, 0, y1h, y1l, 256);
    gru_pointwise<<<PWV_BLOCKS, 256>>>(giA + 384, 768, gh2, y1 + 128, 256, bih0b, bhh0b,
                                       nullptr, 0, y0h + 128, y0l + 128, 256);

    // ---- merged layer-1 GEMMs: giA = y0 @ [W1f|W1b] (6cb), giB = y1 @ W1b (3cb) ----
    sgemm_dual<<<dim3(9, 2000), 256, PSMEM>>>(
        y0h, y0l, 256, pw1, pw1_l, giA, 768,
        y1h, y1l, 256, pw1b, pw1b_l, giB, 384,
        8, 6, 2000);

    // f0' = cell_f1(y0, 0)   b1' = cell_b1(y1, 0)
    gru_pointwise<<<PWV_BLOCKS, 256>>>(giA, 768, nullptr, nullptr, 0, bih1f, bhh1f,
                                       hhb, 256, nullptr, nullptr, 0);
    gru_pointwise<<<PWV_BLOCKS, 256>>>(giB, 384, nullptr, nullptr, 0, bih1b, bhh1b,
                                       hb1, 128, hb1h, hb1l, 128);

    // b0' = cell_b1(y0, b1')
    sgemm_dual<<<dim3(3, 2000), 256, PSMEM>>>(
        hb1h, hb1l, 128, ph1b, ph1b_l, gh, 384,
        hb1h, hb1l, 128, ph1b, ph1b_l, gh, 384,
        4, 1000, 100000);
    gru_pointwise<<<PWV_BLOCKS, 256>>>(giA + 384, 768, gh, hb1, 128, bih1b, bhh1b,
                                       hhb + 128, 256, nullptr, nullptr, 0);

    // ---- logits, segment softmaxes (gumbel fused into prep), weighted scatter ----
    logits_kernel<<<(MM * 32) / 256, 256>>>(hhb, wcon, bcon, logits);
    init_kernel<<<(BB * NN * HH + 255) / 256, 256>>>(out, mxh, mxs, sh, ss);
    prep_kernel<<<MM / 256, 256>>>(logits, src, av, mxh, mxs);
    sum_kernel<<<MM / 256, 256>>>(logits, av, src, mxh, mxs, sh, ss);
    scatter_kernel<<<EE, 128>>>(h, tgt, src, logits, av, mxh, mxs, sh, ss, out);
}